// round 13
// baseline (speedup 1.0000x reference)
#include <cuda_runtime.h>
#include <cuda_fp16.h>
#include <cstdint>

// ===========================================================================
// SSRupsampling via HMMA (mma.sync m16n8k16, fp32 accum), fp16 split.
// 1x1 GEMMs: 3-product (full fp32-grade). Conv GEMMs: 2-product (weight
// hi+lo x act hi). Conv B = shifted view of S-MAJOR [pix,512] act
// (r = s*S + img*96 + l); uniform s per 128-row N-tile -> invalid taps
// skipped. 128x128 block tile, 32x64 warp tile, 256 thr, 2 CTA/SM,
// swizzled smem. PROD2: 3-tile stages x 4-deep pipeline; PROD3: 4-tile x 3.
// Single __syncthreads per chunk. Shuffles fused into epilogues.
// ===========================================================================

// ------------------------------ scratch -----------------------------------
__device__ __half g_aHi[36864L * 512], g_aLo[36864L * 512];
__device__ __half g_bHi[36864L * 512], g_bLo[36864L * 512];
__device__ __half g_cHi[18432 * 512],  g_cLo[18432 * 512];
__device__ __half g_B2hi[9216 * 512],  g_B2lo[9216 * 512];
__device__ __half g_wch_hi[512 * 2048], g_wch_lo[512 * 2048];
__device__ __half g_ww_hi[1024 * 512],  g_ww_lo[1024 * 512];
__device__ __half g_wH_hi[1024 * 512],  g_wH_lo[1024 * 512];
__device__ __half g_wlr_hi[512 * 4608], g_wlr_lo[512 * 4608];
__device__ __half g_wdu_hi[512 * 4608], g_wdu_lo[512 * 4608];

// ------------------------------ helpers -----------------------------------
__device__ __forceinline__ uint32_t smem_u32(const void* p) {
    uint32_t a;
    asm("{ .reg .u64 t; cvta.to.shared.u64 t, %1; cvt.u32.u64 %0, t; }"
        : "=r"(a) : "l"(p));
    return a;
}
__device__ __forceinline__ void ldsm_x4(uint32_t* r, uint32_t addr) {
    asm volatile("ldmatrix.sync.aligned.m8n8.x4.shared.b16 {%0,%1,%2,%3}, [%4];"
                 : "=r"(r[0]), "=r"(r[1]), "=r"(r[2]), "=r"(r[3]) : "r"(addr));
}
__device__ __forceinline__ void mma16816(float* c, const uint32_t* a,
                                         const uint32_t* b) {
    asm volatile(
        "mma.sync.aligned.m16n8k16.row.col.f32.f16.f16.f32 "
        "{%0,%1,%2,%3}, {%4,%5,%6,%7}, {%8,%9}, {%0,%1,%2,%3};"
        : "+f"(c[0]), "+f"(c[1]), "+f"(c[2]), "+f"(c[3])
        : "r"(a[0]), "r"(a[1]), "r"(a[2]), "r"(a[3]), "r"(b[0]), "r"(b[1]));
}
__device__ __forceinline__ void cp16(uint32_t sa, const void* ga) {
    asm volatile("cp.async.cg.shared.global [%0], [%1], 16;"
                 :: "r"(sa), "l"(ga));
}
__device__ __forceinline__ void cp16p(uint32_t sa, const void* ga, int sz) {
    asm volatile("cp.async.cg.shared.global [%0], [%1], 16, %2;"
                 :: "r"(sa), "l"(ga), "r"(sz));
}

#define BK 32
#define TILE_BYTES 8192            // 128 rows x 64B, swizzled
#define SMEM_TOTAL 98304           // both variants: 96 KB per CTA

// swizzled byte offset of the 16B unit (row, lcol), row 0..127, lcol 0..3
__device__ __forceinline__ uint32_t swz(int row, int lcol) {
    return (uint32_t)((row >> 1) * 128 +
                      ((((row & 1) * 4 + lcol) ^ ((row >> 1) & 7)) * 16));
}

// ---------------------------------------------------------------------------
// GEMM: D[m,n] = sum_k A[m,k]*B[n,k], fp16 split, fp32 accum.
// PROD2=0: Ah*Bh + Ah*Bl + Al*Bh (4-tile stages, 3-deep pipeline).
// PROD2=1: Ah*Bh + Al*Bh (3-tile stages, 4-deep pipeline; B-lo never loaded).
// Block tile 128x128, BK=32, 256 threads (8 warps, 4m x 2n), warp 32x64.
// conv!=0: B read from S-MAJOR [Npix,512] act; uniform s per N-tile;
// K-loop covers valid taps only; per-row l-mask in loader.
// Modes: 1 split [pix,512]; 3 conv bias+relu split [pix,512];
//        4 bias+relu NCHW scatter; 5 split + H-shuffle; 6 split + W-shuffle.
// wantLo: write lo half of split outputs (0 when consumer is 2-product).
// ---------------------------------------------------------------------------
template <int PROD2>
__global__ __launch_bounds__(256, 2)
void gemm_hmma(const __half* __restrict__ Ahi, const __half* __restrict__ Alo,
               const __half* __restrict__ Bhi, const __half* __restrict__ Blo,
               int K, int Kb, int conv, int S, int mode, int wantLo,
               const float* __restrict__ bias, float* __restrict__ outF,
               __half* __restrict__ outHi, __half* __restrict__ outLo) {
    constexpr int NT   = PROD2 ? 3 : 4;            // tiles per stage
    constexpr int STG  = NT * TILE_BYTES;          // stage bytes
    constexpr int NST  = PROD2 ? 4 : 3;            // pipeline depth
    constexpr int OFF_AHI = 0;
    constexpr int OFF_ALO = TILE_BYTES;
    constexpr int OFF_BHI = 2 * TILE_BYTES;
    constexpr int OFF_BLO = 3 * TILE_BYTES;        // PROD3 only

    extern __shared__ char smem[];
    const uint32_t sb = smem_u32(smem);
    const int tid = threadIdx.x;
    const int lane = tid & 31, wid = tid >> 5;
    const int wm = wid >> 1, wn = wid & 1;
    const int m0 = blockIdx.x * 128;
    const long n0 = (long)blockIdx.y * 128;

    const __half* gA0 = Ahi + (long)m0 * K;
    const __half* gA1 = Alo + (long)m0 * K;
    const __half* gB0 = Bhi + n0 * Kb;
    const __half* gB1 = Blo + n0 * Kb;

    const int lrow0 = tid >> 2, lcol = tid & 3;
    const int lrow1 = lrow0 + 64;
    const uint32_t sw0 = swz(lrow0, lcol);
    const uint32_t sw1 = swz(lrow1, lcol);

    // conv geometry: s uniform per tile; l = r % 96
    int l0 = 0, l1 = 0, nds = 3, dsmin = -1;
    if (conv) {
        const int sTile = (int)(n0 / S);
        l0 = (int)((n0 + lrow0) % 96);
        l1 = (int)((n0 + lrow1) % 96);
        nds = (sTile == 1) ? 3 : 2;
        dsmin = (sTile == 0) ? 0 : -1;
    }

    const int lg = lane >> 3, lr = lane & 7;
    const uint32_t abase = swz(wm * 32 + (lg & 1) * 8 + lr, lg >> 1);
    const uint32_t bbase = swz(wn * 64 + (lg >> 1) * 8 + lr, lg & 1);

    float acc[2][8][4];
    #pragma unroll
    for (int i = 0; i < 2; i++)
        #pragma unroll
        for (int j = 0; j < 8; j++)
            #pragma unroll
            for (int c = 0; c < 4; c++) acc[i][j][c] = 0.f;

    const int nC = conv ? (3 * nds * 16) : (K / BK);

    auto issue = [&](int kc) {
        const uint32_t so = sb + (kc % NST) * STG;
        if (conv) {
            const int ti = kc >> 4;
            const int dlm = ti / nds - 1;
            const int dsm = dsmin + ti % nds;
            const int t = (dlm + 1) * 3 + (dsm + 1);
            const int koff = (kc & 15) * 32 + lcol * 8;
            const long ga0 = (long)lrow0 * K + t * 512 + koff;
            const long ga1 = (long)lrow1 * K + t * 512 + koff;
            cp16(so + OFF_AHI + sw0, gA0 + ga0);
            cp16(so + OFF_AHI + sw1, gA0 + ga1);
            cp16(so + OFF_ALO + sw0, gA1 + ga0);
            cp16(so + OFF_ALO + sw1, gA1 + ga1);
            const long rs = (long)(dlm + dsm * S) * Kb;
            const int v0 = ((unsigned)(l0 + dlm) < 96u) ? 16 : 0;
            const int v1 = ((unsigned)(l1 + dlm) < 96u) ? 16 : 0;
            const long gb0 = (long)lrow0 * Kb + rs + koff;
            const long gb1 = (long)lrow1 * Kb + rs + koff;
            cp16p(so + OFF_BHI + sw0, gB0 + gb0, v0);
            cp16p(so + OFF_BHI + sw1, gB0 + gb1, v1);
            if (!PROD2) {
                cp16p(so + OFF_BLO + sw0, gB1 + gb0, v0);
                cp16p(so + OFF_BLO + sw1, gB1 + gb1, v1);
            }
        } else {
            const long kb = (long)kc * BK;
            const long ga0 = (long)lrow0 * K + kb + lcol * 8;
            const long ga1 = (long)lrow1 * K + kb + lcol * 8;
            cp16(so + OFF_AHI + sw0, gA0 + ga0);
            cp16(so + OFF_AHI + sw1, gA0 + ga1);
            cp16(so + OFF_ALO + sw0, gA1 + ga0);
            cp16(so + OFF_ALO + sw1, gA1 + ga1);
            const long gb0 = (long)lrow0 * Kb + kb + lcol * 8;
            const long gb1 = (long)lrow1 * Kb + kb + lcol * 8;
            cp16(so + OFF_BHI + sw0, gB0 + gb0);
            cp16(so + OFF_BHI + sw1, gB0 + gb1);
            if (!PROD2) {
                cp16(so + OFF_BLO + sw0, gB1 + gb0);
                cp16(so + OFF_BLO + sw1, gB1 + gb1);
            }
        }
        asm volatile("cp.async.commit_group;" ::: "memory");
    };

    // prologue: NST-1 chunks in flight
    #pragma unroll
    for (int i = 0; i < NST - 1; i++) issue(i);

    for (int kc = 0; kc < nC; kc++) {
        // wait until chunk kc complete: allow min(NST-2, nC-1-kc) newer groups
        const int newer = nC - 1 - kc;
        if (NST == 4 && newer >= 2) {
            asm volatile("cp.async.wait_group 2;" ::: "memory");
        } else if (newer >= 1 && (NST - 2) >= 1) {
            asm volatile("cp.async.wait_group 1;" ::: "memory");
        } else {
            asm volatile("cp.async.wait_group 0;" ::: "memory");
        }
        __syncthreads();              // kc data visible; kc-(NST-1) reads done
        if (kc + NST - 1 < nC) issue(kc + NST - 1);

        const uint32_t so = sb + (kc % NST) * STG;
        #pragma unroll
        for (int ks = 0; ks < 2; ks++) {
            const uint32_t axor = ks * 32;
            uint32_t ah[2][4], al[2][4];
            const uint32_t ab = so + OFF_AHI + abase;
            ldsm_x4(ah[0], (ab) ^ axor);
            ldsm_x4(ah[1], (ab + 1024) ^ axor);
            ldsm_x4(al[0], (ab + TILE_BYTES) ^ axor);
            ldsm_x4(al[1], (ab + TILE_BYTES + 1024) ^ axor);
            const uint32_t bb = so + OFF_BHI + bbase;
            #pragma unroll
            for (int p = 0; p < 4; p++) {
                uint32_t bh[4];
                ldsm_x4(bh, (bb + p * 1024) ^ axor);
                if (!PROD2) {
                    uint32_t bl[4];
                    ldsm_x4(bl, (bb + p * 1024 + TILE_BYTES) ^ axor);
                    #pragma unroll
                    for (int mi = 0; mi < 2; mi++) {
                        mma16816(acc[mi][2 * p],     ah[mi], bh);
                        mma16816(acc[mi][2 * p],     ah[mi], bl);
                        mma16816(acc[mi][2 * p],     al[mi], bh);
                        mma16816(acc[mi][2 * p + 1], ah[mi], bh + 2);
                        mma16816(acc[mi][2 * p + 1], ah[mi], bl + 2);
                        mma16816(acc[mi][2 * p + 1], al[mi], bh + 2);
                    }
                } else {
                    #pragma unroll
                    for (int mi = 0; mi < 2; mi++) {
                        mma16816(acc[mi][2 * p],     ah[mi], bh);
                        mma16816(acc[mi][2 * p],     al[mi], bh);
                        mma16816(acc[mi][2 * p + 1], ah[mi], bh + 2);
                        mma16816(acc[mi][2 * p + 1], al[mi], bh + 2);
                    }
                }
            }
        }
    }

    // ---------------- epilogue -------------------------------------------
    const int mrow = m0 + wm * 32 + (lane >> 2);
    const int nrow = wn * 64 + 2 * (lane & 3);
    #pragma unroll
    for (int mi = 0; mi < 2; mi++) {
        #pragma unroll
        for (int nj = 0; nj < 8; nj++) {
            #pragma unroll
            for (int ci = 0; ci < 4; ci++) {
                const int m = mrow + mi * 16 + (ci >> 1) * 8;
                const long pix = n0 + nrow + nj * 8 + (ci & 1);
                float v = acc[mi][nj][ci];
                if (mode == 3 || mode == 4) v = fmaxf(v + bias[m], 0.f);
                long oidx = -1;
                if (mode == 1 || mode == 3) {
                    oidx = pix * 512 + m;
                } else if (mode == 4) {
                    // final NCHW scatter from DU s-major rows
                    int p = (int)pix;
                    int sD = p / 12288, rem = p % 12288;
                    int img = rem / 96, w2 = rem % 96;
                    int n = img >> 5, ckH = img & 31;
                    int h = ckH * 3 + sD;
                    outF[(((long)n * 512 + m) * 96 + h) * 96 + w2] = v;
                    continue;
                } else if (mode == 5) {
                    // stage2: H-shuffle -> LR act (s-major)
                    int p = (int)pix;
                    int n = p / 2304, rem = p - n * 2304;
                    int h = rem / 48, w = rem - h * 48;
                    int h2 = 2 * h + (m >> 9);
                    int ckW = w / 3, s = w - ckW * 3;
                    long r = (long)s * 6144 + (n * 16 + ckW) * 96 + h2;
                    oidx = r * 512 + (m & 511);
                } else {
                    // mode 6: w_H out -> DU act (s-major)
                    int p = (int)pix;
                    int sL = p / 6144, rem = p % 6144;
                    int img = rem / 96, h2 = rem % 96;
                    int n = img >> 4, ckW = img & 15;
                    int w = ckW * 3 + sL;
                    int w2 = 2 * w + (m >> 9);
                    int ckH = h2 / 3, sD = h2 - ckH * 3;
                    long r = (long)sD * 12288 + (n * 32 + ckH) * 96 + w2;
                    oidx = r * 512 + (m & 511);
                }
                __half h = __float2half_rn(v);
                outHi[oidx] = h;
                if (wantLo)
                    outLo[oidx] = __float2half_rn(v - __half2float(h));
            }
        }
    }
}

// ------------------------- prep kernels -----------------------------------
__device__ __forceinline__ void split_g(float v, __half* hi, __half* lo,
                                        long idx) {
    __half h = __float2half_rn(v);
    hi[idx] = h;
    lo[idx] = __float2half_rn(v - __half2float(h));
}

__global__ void splitW(const float* __restrict__ src, __half* __restrict__ hi,
                       __half* __restrict__ lo, int count) {
    int i = blockIdx.x * 256 + threadIdx.x;
    if (i < count) split_g(src[i], hi, lo, i);
}

// conv weight reorder + split: dst[co*4608 + t*512 + ci]
__global__ void splitWConv(const float* __restrict__ w, __half* __restrict__ hi,
                           __half* __restrict__ lo, int mulL, int mulS) {
    int i = blockIdx.x * 256 + threadIdx.x;
    int ci = i & 511;
    int t = (i >> 9) % 9;
    int co = i / 4608;
    int dl = t / 3, ds = t % 3;
    float v = w[(long)co * 4608 + ci * 9 + dl * mulL + ds * mulS];
    split_g(v, hi, lo, (long)co * 4608 + t * 512 + ci);
}

// x[n,c,h,w] -> B[pix(n,h,w), c] split
__global__ void gatherX(const float* __restrict__ x, __half* __restrict__ bhi,
                        __half* __restrict__ blo) {
    int i = blockIdx.x * 256 + threadIdx.x;
    int c4 = i & 511;
    int pix = i >> 9;
    int n = pix / 2304;
    int p = pix - n * 2304;
    const float* xs = x + ((long)n * 2048 + c4 * 4) * 2304 + p;
    long o = (long)pix * 2048 + c4 * 4;
    split_g(xs[0],    bhi, blo, o + 0);
    split_g(xs[2304], bhi, blo, o + 1);
    split_g(xs[4608], bhi, blo, o + 2);
    split_g(xs[6912], bhi, blo, o + 3);
}

// ---------------------------------------------------------------------------
// kernel_launch.  Inputs: x, w_channel, w_w, w_H, w_lr, b_lr, w_du, b_du
// ---------------------------------------------------------------------------
extern "C" void kernel_launch(void* const* d_in, const int* in_sizes, int n_in,
                              void* d_out, int out_size) {
    const float* x         = (const float*)d_in[0];
    const float* w_channel = (const float*)d_in[1];
    const float* w_w       = (const float*)d_in[2];
    const float* w_H       = (const float*)d_in[3];
    const float* w_lr      = (const float*)d_in[4];
    const float* b_lr      = (const float*)d_in[5];
    const float* w_du      = (const float*)d_in[6];
    const float* b_du      = (const float*)d_in[7];
    float* out = (float*)d_out;

    __half *aHi, *aLo, *bHi, *bLo, *cHi, *cLo, *B2hi, *B2lo;
    __half *wch_hi, *wch_lo, *ww_hi, *ww_lo, *wH_hi, *wH_lo;
    __half *wlr_hi, *wlr_lo, *wdu_hi, *wdu_lo;
    cudaGetSymbolAddress((void**)&aHi, g_aHi);
    cudaGetSymbolAddress((void**)&aLo, g_aLo);
    cudaGetSymbolAddress((void**)&bHi, g_bHi);
    cudaGetSymbolAddress((void**)&bLo, g_bLo);
    cudaGetSymbolAddress((void**)&cHi, g_cHi);
    cudaGetSymbolAddress((void**)&cLo, g_cLo);
    cudaGetSymbolAddress((void**)&B2hi, g_B2hi);
    cudaGetSymbolAddress((void**)&B2lo, g_B2lo);
    cudaGetSymbolAddress((void**)&wch_hi, g_wch_hi);
    cudaGetSymbolAddress((void**)&wch_lo, g_wch_lo);
    cudaGetSymbolAddress((void**)&ww_hi, g_ww_hi);
    cudaGetSymbolAddress((void**)&ww_lo, g_ww_lo);
    cudaGetSymbolAddress((void**)&wH_hi, g_wH_hi);
    cudaGetSymbolAddress((void**)&wH_lo, g_wH_lo);
    cudaGetSymbolAddress((void**)&wlr_hi, g_wlr_hi);
    cudaGetSymbolAddress((void**)&wlr_lo, g_wlr_lo);
    cudaGetSymbolAddress((void**)&wdu_hi, g_wdu_hi);
    cudaGetSymbolAddress((void**)&wdu_lo, g_wdu_lo);

    cudaFuncSetAttribute(gemm_hmma<0>, cudaFuncAttributeMaxDynamicSharedMemorySize,
                         SMEM_TOTAL);
    cudaFuncSetAttribute(gemm_hmma<1>, cudaFuncAttributeMaxDynamicSharedMemorySize,
                         SMEM_TOTAL);

    // weight prep
    splitW<<<(512 * 2048) / 256, 256>>>(w_channel, wch_hi, wch_lo, 512 * 2048);
    splitW<<<(1024 * 512) / 256, 256>>>(w_w, ww_hi, ww_lo, 1024 * 512);
    splitW<<<(1024 * 512) / 256, 256>>>(w_H, wH_hi, wH_lo, 1024 * 512);
    splitWConv<<<(512 * 4608) / 256, 256>>>(w_lr, wlr_hi, wlr_lo, 3, 1);
    splitWConv<<<(512 * 4608) / 256, 256>>>(w_du, wdu_hi, wdu_lo, 1, 3);

    // stage 1: split(x) -> a [9216,2048]; y1 = w_channel @ x -> split B2
    gatherX<<<(9216 * 512) / 256, 256>>>(x, aHi, aLo);
    gemm_hmma<0><<<dim3(4, 72), 256, SMEM_TOTAL>>>(
        wch_hi, wch_lo, aHi, aLo, 2048, 2048, 0, 0, 1, 1, nullptr,
        nullptr, B2hi, B2lo);

    // stage 2: w_w @ y1, epilogue = H-shuffle -> LR act (s-major, hi only)
    gemm_hmma<0><<<dim3(8, 72), 256, SMEM_TOTAL>>>(
        ww_hi, ww_lo, B2hi, B2lo, 512, 512, 0, 0, 5, 0, nullptr,
        nullptr, bHi, bLo);

    // convLR pass 1 (S=6144, 2-product) -> c hi only
    gemm_hmma<1><<<dim3(4, 144), 256, SMEM_TOTAL>>>(
        wlr_hi, wlr_lo, bHi, bLo, 4608, 512, 1, 6144, 3, 0, b_lr,
        nullptr, cHi, cLo);

    // convLR pass 2 (2-product) -> a hi+lo (feeds 3-product w_H)
    gemm_hmma<1><<<dim3(4, 144), 256, SMEM_TOTAL>>>(
        wlr_hi, wlr_lo, cHi, cLo, 4608, 512, 1, 6144, 3, 1, b_lr,
        nullptr, aHi, aLo);

    // w_H stage (3-product): epilogue = W-shuffle -> DU act (hi only)
    gemm_hmma<0><<<dim3(8, 144), 256, SMEM_TOTAL>>>(
        wH_hi, wH_lo, aHi, aLo, 512, 512, 0, 0, 6, 0, nullptr,
        nullptr, bHi, bLo);

    // convDU pass 1 (S=12288, 2-product) -> a hi only
    gemm_hmma<1><<<dim3(4, 288), 256, SMEM_TOTAL>>>(
        wdu_hi, wdu_lo, bHi, bLo, 4608, 512, 1, 12288, 3, 0, b_du,
        nullptr, aHi, aLo);

    // convDU pass 2 (2-product) -> final NCHW output
    gemm_hmma<1><<<dim3(4, 288), 256, SMEM_TOTAL>>>(
        wdu_hi, wdu_lo, aHi, aLo, 4608, 512, 1, 12288, 4, 0, b_du,
        out, nullptr, nullptr);
}

// round 14
// speedup vs baseline: 1.2728x; 1.2728x over previous
#include <cuda_runtime.h>
#include <cuda_fp16.h>
#include <cstdint>

// ===========================================================================
// SSRupsampling via HMMA (mma.sync m16n8k16, fp32 accum), fp16 split.
// 1x1 GEMMs: 3-product. convLR: 2-product (Wh+Wl x Ah). convDU: 1-product
// (Wh x Ah, pure fp16 weights). Conv B = shifted view of S-MAJOR [pix,512]
// act (r = s*S + img*96 + l); uniform s per 128-row N-tile -> invalid taps
// skipped. 128x128 block tile, 32x64 warp tile, 256 thr, 2 CTA/SM,
// swizzled smem; stage = NP+1 tiles, pipeline depth 3 (NP3) / 4 (NP2, NP1).
// Single __syncthreads per chunk. Shuffles fused into epilogues.
// ===========================================================================

// ------------------------------ scratch -----------------------------------
__device__ __half g_aHi[36864L * 512], g_aLo[36864L * 512];
__device__ __half g_bHi[36864L * 512], g_bLo[36864L * 512];
__device__ __half g_cHi[18432 * 512],  g_cLo[18432 * 512];
__device__ __half g_B2hi[9216 * 512],  g_B2lo[9216 * 512];
__device__ __half g_wch_hi[512 * 2048], g_wch_lo[512 * 2048];
__device__ __half g_ww_hi[1024 * 512],  g_ww_lo[1024 * 512];
__device__ __half g_wH_hi[1024 * 512],  g_wH_lo[1024 * 512];
__device__ __half g_wlr_hi[512 * 4608], g_wlr_lo[512 * 4608];
__device__ __half g_wdu_hi[512 * 4608], g_wdu_lo[512 * 4608];

// ------------------------------ helpers -----------------------------------
__device__ __forceinline__ uint32_t smem_u32(const void* p) {
    uint32_t a;
    asm("{ .reg .u64 t; cvta.to.shared.u64 t, %1; cvt.u32.u64 %0, t; }"
        : "=r"(a) : "l"(p));
    return a;
}
__device__ __forceinline__ void ldsm_x4(uint32_t* r, uint32_t addr) {
    asm volatile("ldmatrix.sync.aligned.m8n8.x4.shared.b16 {%0,%1,%2,%3}, [%4];"
                 : "=r"(r[0]), "=r"(r[1]), "=r"(r[2]), "=r"(r[3]) : "r"(addr));
}
__device__ __forceinline__ void mma16816(float* c, const uint32_t* a,
                                         const uint32_t* b) {
    asm volatile(
        "mma.sync.aligned.m16n8k16.row.col.f32.f16.f16.f32 "
        "{%0,%1,%2,%3}, {%4,%5,%6,%7}, {%8,%9}, {%0,%1,%2,%3};"
        : "+f"(c[0]), "+f"(c[1]), "+f"(c[2]), "+f"(c[3])
        : "r"(a[0]), "r"(a[1]), "r"(a[2]), "r"(a[3]), "r"(b[0]), "r"(b[1]));
}
__device__ __forceinline__ void cp16(uint32_t sa, const void* ga) {
    asm volatile("cp.async.cg.shared.global [%0], [%1], 16;"
                 :: "r"(sa), "l"(ga));
}
__device__ __forceinline__ void cp16p(uint32_t sa, const void* ga, int sz) {
    asm volatile("cp.async.cg.shared.global [%0], [%1], 16, %2;"
                 :: "r"(sa), "l"(ga), "r"(sz));
}

#define BK 32
#define TILE_BYTES 8192            // 128 rows x 64B, swizzled
#define SMEM_TOTAL 98304           // all variants: <= 96 KB per CTA

// swizzled byte offset of the 16B unit (row, lcol), row 0..127, lcol 0..3
__device__ __forceinline__ uint32_t swz(int row, int lcol) {
    return (uint32_t)((row >> 1) * 128 +
                      ((((row & 1) * 4 + lcol) ^ ((row >> 1) & 7)) * 16));
}

// ---------------------------------------------------------------------------
// GEMM: D[m,n] = sum_k A[m,k]*B[n,k], fp16 split, fp32 accum.
// NP=3: Ah*Bh + Ah*Bl + Al*Bh (4-tile stage, depth 3).
// NP=2: Ah*Bh + Al*Bh        (3-tile stage, depth 4; B-lo never loaded).
// NP=1: Ah*Bh                (2-tile stage, depth 4; only hi tiles).
// Block tile 128x128, BK=32, 256 threads (8 warps, 4m x 2n), warp 32x64.
// conv!=0: B from S-MAJOR [Npix,512] act; uniform s per N-tile; valid taps
// only; per-row l-mask in loader.
// Modes: 1 split [pix,512]; 3 conv bias+relu split [pix,512];
//        4 bias+relu NCHW scatter; 5 split + H-shuffle; 6 split + W-shuffle.
// wantLo: write lo half of split outputs.
// ---------------------------------------------------------------------------
template <int NP>
__global__ __launch_bounds__(256, 2)
void gemm_hmma(const __half* __restrict__ Ahi, const __half* __restrict__ Alo,
               const __half* __restrict__ Bhi, const __half* __restrict__ Blo,
               int K, int Kb, int conv, int S, int mode, int wantLo,
               const float* __restrict__ bias, float* __restrict__ outF,
               __half* __restrict__ outHi, __half* __restrict__ outLo) {
    constexpr int NT  = NP + 1;                    // tiles per stage
    constexpr int STG = NT * TILE_BYTES;
    constexpr int NST = (NP == 3) ? 3 : 4;         // pipeline depth
    constexpr int OFF_AHI = 0;
    constexpr int OFF_ALO = TILE_BYTES;            // NP>=2 only
    constexpr int OFF_BHI = (NP >= 2) ? 2 * TILE_BYTES : TILE_BYTES;
    constexpr int OFF_BLO = 3 * TILE_BYTES;        // NP==3 only

    extern __shared__ char smem[];
    const uint32_t sb = smem_u32(smem);
    const int tid = threadIdx.x;
    const int lane = tid & 31, wid = tid >> 5;
    const int wm = wid >> 1, wn = wid & 1;
    const int m0 = blockIdx.x * 128;
    const long n0 = (long)blockIdx.y * 128;

    const __half* gA0 = Ahi + (long)m0 * K;
    const __half* gA1 = Alo + (long)m0 * K;
    const __half* gB0 = Bhi + n0 * Kb;
    const __half* gB1 = Blo + n0 * Kb;

    const int lrow0 = tid >> 2, lcol = tid & 3;
    const int lrow1 = lrow0 + 64;
    const uint32_t sw0 = swz(lrow0, lcol);
    const uint32_t sw1 = swz(lrow1, lcol);

    // conv geometry: s uniform per tile; l = r % 96
    int l0 = 0, l1 = 0, nds = 3, dsmin = -1;
    if (conv) {
        const int sTile = (int)(n0 / S);
        l0 = (int)((n0 + lrow0) % 96);
        l1 = (int)((n0 + lrow1) % 96);
        nds = (sTile == 1) ? 3 : 2;
        dsmin = (sTile == 0) ? 0 : -1;
    }

    const int lg = lane >> 3, lr = lane & 7;
    const uint32_t abase = swz(wm * 32 + (lg & 1) * 8 + lr, lg >> 1);
    const uint32_t bbase = swz(wn * 64 + (lg >> 1) * 8 + lr, lg & 1);

    float acc[2][8][4];
    #pragma unroll
    for (int i = 0; i < 2; i++)
        #pragma unroll
        for (int j = 0; j < 8; j++)
            #pragma unroll
            for (int c = 0; c < 4; c++) acc[i][j][c] = 0.f;

    const int nC = conv ? (3 * nds * 16) : (K / BK);

    auto issue = [&](int kc) {
        const uint32_t so = sb + (kc % NST) * STG;
        if (conv) {
            const int ti = kc >> 4;
            const int dlm = ti / nds - 1;
            const int dsm = dsmin + ti % nds;
            const int t = (dlm + 1) * 3 + (dsm + 1);
            const int koff = (kc & 15) * 32 + lcol * 8;
            const long ga0 = (long)lrow0 * K + t * 512 + koff;
            const long ga1 = (long)lrow1 * K + t * 512 + koff;
            cp16(so + OFF_AHI + sw0, gA0 + ga0);
            cp16(so + OFF_AHI + sw1, gA0 + ga1);
            if (NP >= 2) {
                cp16(so + OFF_ALO + sw0, gA1 + ga0);
                cp16(so + OFF_ALO + sw1, gA1 + ga1);
            }
            const long rs = (long)(dlm + dsm * S) * Kb;
            const int v0 = ((unsigned)(l0 + dlm) < 96u) ? 16 : 0;
            const int v1 = ((unsigned)(l1 + dlm) < 96u) ? 16 : 0;
            const long gb0 = (long)lrow0 * Kb + rs + koff;
            const long gb1 = (long)lrow1 * Kb + rs + koff;
            cp16p(so + OFF_BHI + sw0, gB0 + gb0, v0);
            cp16p(so + OFF_BHI + sw1, gB0 + gb1, v1);
            if (NP == 3) {
                cp16p(so + OFF_BLO + sw0, gB1 + gb0, v0);
                cp16p(so + OFF_BLO + sw1, gB1 + gb1, v1);
            }
        } else {
            const long kb = (long)kc * BK;
            const long ga0 = (long)lrow0 * K + kb + lcol * 8;
            const long ga1 = (long)lrow1 * K + kb + lcol * 8;
            cp16(so + OFF_AHI + sw0, gA0 + ga0);
            cp16(so + OFF_AHI + sw1, gA0 + ga1);
            if (NP >= 2) {
                cp16(so + OFF_ALO + sw0, gA1 + ga0);
                cp16(so + OFF_ALO + sw1, gA1 + ga1);
            }
            const long gb0 = (long)lrow0 * Kb + kb + lcol * 8;
            const long gb1 = (long)lrow1 * Kb + kb + lcol * 8;
            cp16(so + OFF_BHI + sw0, gB0 + gb0);
            cp16(so + OFF_BHI + sw1, gB0 + gb1);
            if (NP == 3) {
                cp16(so + OFF_BLO + sw0, gB1 + gb0);
                cp16(so + OFF_BLO + sw1, gB1 + gb1);
            }
        }
        asm volatile("cp.async.commit_group;" ::: "memory");
    };

    // prologue: NST-1 chunks in flight
    #pragma unroll
    for (int i = 0; i < NST - 1; i++) issue(i);

    for (int kc = 0; kc < nC; kc++) {
        const int newer = nC - 1 - kc;
        if (NST == 4 && newer >= 2) {
            asm volatile("cp.async.wait_group 2;" ::: "memory");
        } else if (newer >= 1) {
            asm volatile("cp.async.wait_group 1;" ::: "memory");
        } else {
            asm volatile("cp.async.wait_group 0;" ::: "memory");
        }
        __syncthreads();              // kc data visible; kc-(NST-1) reads done
        if (kc + NST - 1 < nC) issue(kc + NST - 1);

        const uint32_t so = sb + (kc % NST) * STG;
        #pragma unroll
        for (int ks = 0; ks < 2; ks++) {
            const uint32_t axor = ks * 32;
            uint32_t ah[2][4], al[2][4];
            const uint32_t ab = so + OFF_AHI + abase;
            ldsm_x4(ah[0], (ab) ^ axor);
            ldsm_x4(ah[1], (ab + 1024) ^ axor);
            if (NP >= 2) {
                ldsm_x4(al[0], (ab + TILE_BYTES) ^ axor);
                ldsm_x4(al[1], (ab + TILE_BYTES + 1024) ^ axor);
            }
            const uint32_t bb = so + OFF_BHI + bbase;
            #pragma unroll
            for (int p = 0; p < 4; p++) {
                uint32_t bh[4];
                ldsm_x4(bh, (bb + p * 1024) ^ axor);
                if (NP == 3) {
                    uint32_t bl[4];
                    ldsm_x4(bl, (bb + p * 1024 + TILE_BYTES) ^ axor);
                    #pragma unroll
                    for (int mi = 0; mi < 2; mi++) {
                        mma16816(acc[mi][2 * p],     ah[mi], bh);
                        mma16816(acc[mi][2 * p],     ah[mi], bl);
                        mma16816(acc[mi][2 * p],     al[mi], bh);
                        mma16816(acc[mi][2 * p + 1], ah[mi], bh + 2);
                        mma16816(acc[mi][2 * p + 1], ah[mi], bl + 2);
                        mma16816(acc[mi][2 * p + 1], al[mi], bh + 2);
                    }
                } else if (NP == 2) {
                    #pragma unroll
                    for (int mi = 0; mi < 2; mi++) {
                        mma16816(acc[mi][2 * p],     ah[mi], bh);
                        mma16816(acc[mi][2 * p],     al[mi], bh);
                        mma16816(acc[mi][2 * p + 1], ah[mi], bh + 2);
                        mma16816(acc[mi][2 * p + 1], al[mi], bh + 2);
                    }
                } else {
                    #pragma unroll
                    for (int mi = 0; mi < 2; mi++) {
                        mma16816(acc[mi][2 * p],     ah[mi], bh);
                        mma16816(acc[mi][2 * p + 1], ah[mi], bh + 2);
                    }
                }
            }
        }
    }

    // ---------------- epilogue -------------------------------------------
    const int mrow = m0 + wm * 32 + (lane >> 2);
    const int nrow = wn * 64 + 2 * (lane & 3);
    #pragma unroll
    for (int mi = 0; mi < 2; mi++) {
        #pragma unroll
        for (int nj = 0; nj < 8; nj++) {
            #pragma unroll
            for (int ci = 0; ci < 4; ci++) {
                const int m = mrow + mi * 16 + (ci >> 1) * 8;
                const long pix = n0 + nrow + nj * 8 + (ci & 1);
                float v = acc[mi][nj][ci];
                if (mode == 3 || mode == 4) v = fmaxf(v + bias[m], 0.f);
                long oidx = -1;
                if (mode == 1 || mode == 3) {
                    oidx = pix * 512 + m;
                } else if (mode == 4) {
                    // final NCHW scatter from DU s-major rows
                    int p = (int)pix;
                    int sD = p / 12288, rem = p % 12288;
                    int img = rem / 96, w2 = rem % 96;
                    int n = img >> 5, ckH = img & 31;
                    int h = ckH * 3 + sD;
                    outF[(((long)n * 512 + m) * 96 + h) * 96 + w2] = v;
                    continue;
                } else if (mode == 5) {
                    // stage2: H-shuffle -> LR act (s-major)
                    int p = (int)pix;
                    int n = p / 2304, rem = p - n * 2304;
                    int h = rem / 48, w = rem - h * 48;
                    int h2 = 2 * h + (m >> 9);
                    int ckW = w / 3, s = w - ckW * 3;
                    long r = (long)s * 6144 + (n * 16 + ckW) * 96 + h2;
                    oidx = r * 512 + (m & 511);
                } else {
                    // mode 6: w_H out -> DU act (s-major)
                    int p = (int)pix;
                    int sL = p / 6144, rem = p % 6144;
                    int img = rem / 96, h2 = rem % 96;
                    int n = img >> 4, ckW = img & 15;
                    int w = ckW * 3 + sL;
                    int w2 = 2 * w + (m >> 9);
                    int ckH = h2 / 3, sD = h2 - ckH * 3;
                    long r = (long)sD * 12288 + (n * 32 + ckH) * 96 + w2;
                    oidx = r * 512 + (m & 511);
                }
                __half h = __float2half_rn(v);
                outHi[oidx] = h;
                if (wantLo)
                    outLo[oidx] = __float2half_rn(v - __half2float(h));
            }
        }
    }
}

// ------------------------- prep kernels -----------------------------------
__device__ __forceinline__ void split_g(float v, __half* hi, __half* lo,
                                        long idx) {
    __half h = __float2half_rn(v);
    hi[idx] = h;
    lo[idx] = __float2half_rn(v - __half2float(h));
}

__global__ void splitW(const float* __restrict__ src, __half* __restrict__ hi,
                       __half* __restrict__ lo, int count) {
    int i = blockIdx.x * 256 + threadIdx.x;
    if (i < count) split_g(src[i], hi, lo, i);
}

// conv weight reorder + split: dst[co*4608 + t*512 + ci]
__global__ void splitWConv(const float* __restrict__ w, __half* __restrict__ hi,
                           __half* __restrict__ lo, int mulL, int mulS) {
    int i = blockIdx.x * 256 + threadIdx.x;
    int ci = i & 511;
    int t = (i >> 9) % 9;
    int co = i / 4608;
    int dl = t / 3, ds = t % 3;
    float v = w[(long)co * 4608 + ci * 9 + dl * mulL + ds * mulS];
    split_g(v, hi, lo, (long)co * 4608 + t * 512 + ci);
}

// x[n,c,h,w] -> B[pix(n,h,w), c] split
__global__ void gatherX(const float* __restrict__ x, __half* __restrict__ bhi,
                        __half* __restrict__ blo) {
    int i = blockIdx.x * 256 + threadIdx.x;
    int c4 = i & 511;
    int pix = i >> 9;
    int n = pix / 2304;
    int p = pix - n * 2304;
    const float* xs = x + ((long)n * 2048 + c4 * 4) * 2304 + p;
    long o = (long)pix * 2048 + c4 * 4;
    split_g(xs[0],    bhi, blo, o + 0);
    split_g(xs[2304], bhi, blo, o + 1);
    split_g(xs[4608], bhi, blo, o + 2);
    split_g(xs[6912], bhi, blo, o + 3);
}

// ---------------------------------------------------------------------------
// kernel_launch.  Inputs: x, w_channel, w_w, w_H, w_lr, b_lr, w_du, b_du
// ---------------------------------------------------------------------------
extern "C" void kernel_launch(void* const* d_in, const int* in_sizes, int n_in,
                              void* d_out, int out_size) {
    const float* x         = (const float*)d_in[0];
    const float* w_channel = (const float*)d_in[1];
    const float* w_w       = (const float*)d_in[2];
    const float* w_H       = (const float*)d_in[3];
    const float* w_lr      = (const float*)d_in[4];
    const float* b_lr      = (const float*)d_in[5];
    const float* w_du      = (const float*)d_in[6];
    const float* b_du      = (const float*)d_in[7];
    float* out = (float*)d_out;

    __half *aHi, *aLo, *bHi, *bLo, *cHi, *cLo, *B2hi, *B2lo;
    __half *wch_hi, *wch_lo, *ww_hi, *ww_lo, *wH_hi, *wH_lo;
    __half *wlr_hi, *wlr_lo, *wdu_hi, *wdu_lo;
    cudaGetSymbolAddress((void**)&aHi, g_aHi);
    cudaGetSymbolAddress((void**)&aLo, g_aLo);
    cudaGetSymbolAddress((void**)&bHi, g_bHi);
    cudaGetSymbolAddress((void**)&bLo, g_bLo);
    cudaGetSymbolAddress((void**)&cHi, g_cHi);
    cudaGetSymbolAddress((void**)&cLo, g_cLo);
    cudaGetSymbolAddress((void**)&B2hi, g_B2hi);
    cudaGetSymbolAddress((void**)&B2lo, g_B2lo);
    cudaGetSymbolAddress((void**)&wch_hi, g_wch_hi);
    cudaGetSymbolAddress((void**)&wch_lo, g_wch_lo);
    cudaGetSymbolAddress((void**)&ww_hi, g_ww_hi);
    cudaGetSymbolAddress((void**)&ww_lo, g_ww_lo);
    cudaGetSymbolAddress((void**)&wH_hi, g_wH_hi);
    cudaGetSymbolAddress((void**)&wH_lo, g_wH_lo);
    cudaGetSymbolAddress((void**)&wlr_hi, g_wlr_hi);
    cudaGetSymbolAddress((void**)&wlr_lo, g_wlr_lo);
    cudaGetSymbolAddress((void**)&wdu_hi, g_wdu_hi);
    cudaGetSymbolAddress((void**)&wdu_lo, g_wdu_lo);

    cudaFuncSetAttribute(gemm_hmma<3>, cudaFuncAttributeMaxDynamicSharedMemorySize,
                         SMEM_TOTAL);
    cudaFuncSetAttribute(gemm_hmma<2>, cudaFuncAttributeMaxDynamicSharedMemorySize,
                         SMEM_TOTAL);
    cudaFuncSetAttribute(gemm_hmma<1>, cudaFuncAttributeMaxDynamicSharedMemorySize,
                         SMEM_TOTAL);

    // weight prep
    splitW<<<(512 * 2048) / 256, 256>>>(w_channel, wch_hi, wch_lo, 512 * 2048);
    splitW<<<(1024 * 512) / 256, 256>>>(w_w, ww_hi, ww_lo, 1024 * 512);
    splitW<<<(1024 * 512) / 256, 256>>>(w_H, wH_hi, wH_lo, 1024 * 512);
    splitWConv<<<(512 * 4608) / 256, 256>>>(w_lr, wlr_hi, wlr_lo, 3, 1);
    splitWConv<<<(512 * 4608) / 256, 256>>>(w_du, wdu_hi, wdu_lo, 1, 3);

    // stage 1: split(x) -> a [9216,2048]; y1 = w_channel @ x -> split B2
    gatherX<<<(9216 * 512) / 256, 256>>>(x, aHi, aLo);
    gemm_hmma<3><<<dim3(4, 72), 256, SMEM_TOTAL>>>(
        wch_hi, wch_lo, aHi, aLo, 2048, 2048, 0, 0, 1, 1, nullptr,
        nullptr, B2hi, B2lo);

    // stage 2: w_w @ y1, epilogue = H-shuffle -> LR act (s-major, hi only)
    gemm_hmma<3><<<dim3(8, 72), 256, SMEM_TOTAL>>>(
        ww_hi, ww_lo, B2hi, B2lo, 512, 512, 0, 0, 5, 0, nullptr,
        nullptr, bHi, bLo);

    // convLR pass 1 (S=6144, 2-product) -> c hi only
    gemm_hmma<2><<<dim3(4, 144), 256, SMEM_TOTAL>>>(
        wlr_hi, wlr_lo, bHi, bLo, 4608, 512, 1, 6144, 3, 0, b_lr,
        nullptr, cHi, cLo);

    // convLR pass 2 (2-product) -> a hi+lo (feeds 3-product w_H)
    gemm_hmma<2><<<dim3(4, 144), 256, SMEM_TOTAL>>>(
        wlr_hi, wlr_lo, cHi, cLo, 4608, 512, 1, 6144, 3, 1, b_lr,
        nullptr, aHi, aLo);

    // w_H stage (3-product): epilogue = W-shuffle -> DU act (hi only)
    gemm_hmma<3><<<dim3(8, 144), 256, SMEM_TOTAL>>>(
        wH_hi, wH_lo, aHi, aLo, 512, 512, 0, 0, 6, 0, nullptr,
        nullptr, bHi, bLo);

    // convDU pass 1 (S=12288, 1-product fp16 weights) -> a hi only
    gemm_hmma<1><<<dim3(4, 288), 256, SMEM_TOTAL>>>(
        wdu_hi, wdu_lo, bHi, bLo, 4608, 512, 1, 12288, 3, 0, b_du,
        nullptr, aHi, aLo);

    // convDU pass 2 (1-product) -> final NCHW output
    gemm_hmma<1><<<dim3(4, 288), 256, SMEM_TOTAL>>>(
        wdu_hi, wdu_lo, aHi, aLo, 4608, 512, 1, 12288, 4, 0, b_du,
        out, nullptr, nullptr);
}

// round 15
// speedup vs baseline: 1.4896x; 1.1703x over previous
#include <cuda_runtime.h>
#include <cuda_fp16.h>
#include <cstdint>

// ===========================================================================
// SSRupsampling via HMMA (mma.sync m16n8k16, fp32 accum), fp16 split.
// 1x1 GEMMs: 3-product. convLR + convDU: 1-product (pure fp16 weights,
// act-hi). Conv B = shifted view of S-MAJOR [pix,512] act
// (r = s*S + img*96 + l); uniform s per 128-row N-tile -> invalid taps
// skipped. 128x128 block tile, 32x64 warp tile, 256 thr, 2 CTA/SM,
// swizzled smem; stage = NP+1 tiles, pipeline depth 3 (NP3) / 4 (NP2, NP1).
// Single __syncthreads per chunk. Shuffles fused into epilogues.
// ===========================================================================

// ------------------------------ scratch -----------------------------------
__device__ __half g_aHi[36864L * 512], g_aLo[36864L * 512];
__device__ __half g_bHi[36864L * 512], g_bLo[36864L * 512];
__device__ __half g_cHi[18432 * 512],  g_cLo[18432 * 512];
__device__ __half g_B2hi[9216 * 512],  g_B2lo[9216 * 512];
__device__ __half g_wch_hi[512 * 2048], g_wch_lo[512 * 2048];
__device__ __half g_ww_hi[1024 * 512],  g_ww_lo[1024 * 512];
__device__ __half g_wH_hi[1024 * 512],  g_wH_lo[1024 * 512];
__device__ __half g_wlr_hi[512 * 4608], g_wlr_lo[512 * 4608];
__device__ __half g_wdu_hi[512 * 4608], g_wdu_lo[512 * 4608];

// ------------------------------ helpers -----------------------------------
__device__ __forceinline__ uint32_t smem_u32(const void* p) {
    uint32_t a;
    asm("{ .reg .u64 t; cvta.to.shared.u64 t, %1; cvt.u32.u64 %0, t; }"
        : "=r"(a) : "l"(p));
    return a;
}
__device__ __forceinline__ void ldsm_x4(uint32_t* r, uint32_t addr) {
    asm volatile("ldmatrix.sync.aligned.m8n8.x4.shared.b16 {%0,%1,%2,%3}, [%4];"
                 : "=r"(r[0]), "=r"(r[1]), "=r"(r[2]), "=r"(r[3]) : "r"(addr));
}
__device__ __forceinline__ void mma16816(float* c, const uint32_t* a,
                                         const uint32_t* b) {
    asm volatile(
        "mma.sync.aligned.m16n8k16.row.col.f32.f16.f16.f32 "
        "{%0,%1,%2,%3}, {%4,%5,%6,%7}, {%8,%9}, {%0,%1,%2,%3};"
        : "+f"(c[0]), "+f"(c[1]), "+f"(c[2]), "+f"(c[3])
        : "r"(a[0]), "r"(a[1]), "r"(a[2]), "r"(a[3]), "r"(b[0]), "r"(b[1]));
}
__device__ __forceinline__ void cp16(uint32_t sa, const void* ga) {
    asm volatile("cp.async.cg.shared.global [%0], [%1], 16;"
                 :: "r"(sa), "l"(ga));
}
__device__ __forceinline__ void cp16p(uint32_t sa, const void* ga, int sz) {
    asm volatile("cp.async.cg.shared.global [%0], [%1], 16, %2;"
                 :: "r"(sa), "l"(ga), "r"(sz));
}

#define BK 32
#define TILE_BYTES 8192            // 128 rows x 64B, swizzled
#define SMEM_TOTAL 98304           // all variants: <= 96 KB per CTA

// swizzled byte offset of the 16B unit (row, lcol), row 0..127, lcol 0..3
__device__ __forceinline__ uint32_t swz(int row, int lcol) {
    return (uint32_t)((row >> 1) * 128 +
                      ((((row & 1) * 4 + lcol) ^ ((row >> 1) & 7)) * 16));
}

// ---------------------------------------------------------------------------
// GEMM: D[m,n] = sum_k A[m,k]*B[n,k], fp16 split, fp32 accum.
// NP=3: Ah*Bh + Ah*Bl + Al*Bh (4-tile stage, depth 3).
// NP=2: Ah*Bh + Al*Bh        (3-tile stage, depth 4; B-lo never loaded).
// NP=1: Ah*Bh                (2-tile stage, depth 4; only hi tiles).
// Block tile 128x128, BK=32, 256 threads (8 warps, 4m x 2n), warp 32x64.
// conv!=0: B from S-MAJOR [Npix,512] act; uniform s per N-tile; valid taps
// only; per-row l-mask in loader.
// Modes: 1 split [pix,512]; 3 conv bias+relu split [pix,512];
//        4 bias+relu NCHW scatter; 5 split + H-shuffle; 6 split + W-shuffle.
// wantLo: write lo half of split outputs.
// ---------------------------------------------------------------------------
template <int NP>
__global__ __launch_bounds__(256, 2)
void gemm_hmma(const __half* __restrict__ Ahi, const __half* __restrict__ Alo,
               const __half* __restrict__ Bhi, const __half* __restrict__ Blo,
               int K, int Kb, int conv, int S, int mode, int wantLo,
               const float* __restrict__ bias, float* __restrict__ outF,
               __half* __restrict__ outHi, __half* __restrict__ outLo) {
    constexpr int NT  = NP + 1;                    // tiles per stage
    constexpr int STG = NT * TILE_BYTES;
    constexpr int NST = (NP == 3) ? 3 : 4;         // pipeline depth
    constexpr int OFF_AHI = 0;
    constexpr int OFF_ALO = TILE_BYTES;            // NP>=2 only
    constexpr int OFF_BHI = (NP >= 2) ? 2 * TILE_BYTES : TILE_BYTES;
    constexpr int OFF_BLO = 3 * TILE_BYTES;        // NP==3 only

    extern __shared__ char smem[];
    const uint32_t sb = smem_u32(smem);
    const int tid = threadIdx.x;
    const int lane = tid & 31, wid = tid >> 5;
    const int wm = wid >> 1, wn = wid & 1;
    const int m0 = blockIdx.x * 128;
    const long n0 = (long)blockIdx.y * 128;

    const __half* gA0 = Ahi + (long)m0 * K;
    const __half* gA1 = Alo + (long)m0 * K;
    const __half* gB0 = Bhi + n0 * Kb;
    const __half* gB1 = Blo + n0 * Kb;

    const int lrow0 = tid >> 2, lcol = tid & 3;
    const int lrow1 = lrow0 + 64;
    const uint32_t sw0 = swz(lrow0, lcol);
    const uint32_t sw1 = swz(lrow1, lcol);

    // conv geometry: s uniform per tile; l = r % 96
    int l0 = 0, l1 = 0, nds = 3, dsmin = -1;
    if (conv) {
        const int sTile = (int)(n0 / S);
        l0 = (int)((n0 + lrow0) % 96);
        l1 = (int)((n0 + lrow1) % 96);
        nds = (sTile == 1) ? 3 : 2;
        dsmin = (sTile == 0) ? 0 : -1;
    }

    const int lg = lane >> 3, lr = lane & 7;
    const uint32_t abase = swz(wm * 32 + (lg & 1) * 8 + lr, lg >> 1);
    const uint32_t bbase = swz(wn * 64 + (lg >> 1) * 8 + lr, lg & 1);

    float acc[2][8][4];
    #pragma unroll
    for (int i = 0; i < 2; i++)
        #pragma unroll
        for (int j = 0; j < 8; j++)
            #pragma unroll
            for (int c = 0; c < 4; c++) acc[i][j][c] = 0.f;

    const int nC = conv ? (3 * nds * 16) : (K / BK);

    auto issue = [&](int kc) {
        const uint32_t so = sb + (kc % NST) * STG;
        if (conv) {
            const int ti = kc >> 4;
            const int dlm = ti / nds - 1;
            const int dsm = dsmin + ti % nds;
            const int t = (dlm + 1) * 3 + (dsm + 1);
            const int koff = (kc & 15) * 32 + lcol * 8;
            const long ga0 = (long)lrow0 * K + t * 512 + koff;
            const long ga1 = (long)lrow1 * K + t * 512 + koff;
            cp16(so + OFF_AHI + sw0, gA0 + ga0);
            cp16(so + OFF_AHI + sw1, gA0 + ga1);
            if (NP >= 2) {
                cp16(so + OFF_ALO + sw0, gA1 + ga0);
                cp16(so + OFF_ALO + sw1, gA1 + ga1);
            }
            const long rs = (long)(dlm + dsm * S) * Kb;
            const int v0 = ((unsigned)(l0 + dlm) < 96u) ? 16 : 0;
            const int v1 = ((unsigned)(l1 + dlm) < 96u) ? 16 : 0;
            const long gb0 = (long)lrow0 * Kb + rs + koff;
            const long gb1 = (long)lrow1 * Kb + rs + koff;
            cp16p(so + OFF_BHI + sw0, gB0 + gb0, v0);
            cp16p(so + OFF_BHI + sw1, gB0 + gb1, v1);
            if (NP == 3) {
                cp16p(so + OFF_BLO + sw0, gB1 + gb0, v0);
                cp16p(so + OFF_BLO + sw1, gB1 + gb1, v1);
            }
        } else {
            const long kb = (long)kc * BK;
            const long ga0 = (long)lrow0 * K + kb + lcol * 8;
            const long ga1 = (long)lrow1 * K + kb + lcol * 8;
            cp16(so + OFF_AHI + sw0, gA0 + ga0);
            cp16(so + OFF_AHI + sw1, gA0 + ga1);
            if (NP >= 2) {
                cp16(so + OFF_ALO + sw0, gA1 + ga0);
                cp16(so + OFF_ALO + sw1, gA1 + ga1);
            }
            const long gb0 = (long)lrow0 * Kb + kb + lcol * 8;
            const long gb1 = (long)lrow1 * Kb + kb + lcol * 8;
            cp16(so + OFF_BHI + sw0, gB0 + gb0);
            cp16(so + OFF_BHI + sw1, gB0 + gb1);
            if (NP == 3) {
                cp16(so + OFF_BLO + sw0, gB1 + gb0);
                cp16(so + OFF_BLO + sw1, gB1 + gb1);
            }
        }
        asm volatile("cp.async.commit_group;" ::: "memory");
    };

    // prologue: NST-1 chunks in flight
    #pragma unroll
    for (int i = 0; i < NST - 1; i++) issue(i);

    for (int kc = 0; kc < nC; kc++) {
        const int newer = nC - 1 - kc;
        if (NST == 4 && newer >= 2) {
            asm volatile("cp.async.wait_group 2;" ::: "memory");
        } else if (newer >= 1) {
            asm volatile("cp.async.wait_group 1;" ::: "memory");
        } else {
            asm volatile("cp.async.wait_group 0;" ::: "memory");
        }
        __syncthreads();              // kc data visible; kc-(NST-1) reads done
        if (kc + NST - 1 < nC) issue(kc + NST - 1);

        const uint32_t so = sb + (kc % NST) * STG;
        #pragma unroll
        for (int ks = 0; ks < 2; ks++) {
            const uint32_t axor = ks * 32;
            uint32_t ah[2][4], al[2][4];
            const uint32_t ab = so + OFF_AHI + abase;
            ldsm_x4(ah[0], (ab) ^ axor);
            ldsm_x4(ah[1], (ab + 1024) ^ axor);
            if (NP >= 2) {
                ldsm_x4(al[0], (ab + TILE_BYTES) ^ axor);
                ldsm_x4(al[1], (ab + TILE_BYTES + 1024) ^ axor);
            }
            const uint32_t bb = so + OFF_BHI + bbase;
            #pragma unroll
            for (int p = 0; p < 4; p++) {
                uint32_t bh[4];
                ldsm_x4(bh, (bb + p * 1024) ^ axor);
                if (NP == 3) {
                    uint32_t bl[4];
                    ldsm_x4(bl, (bb + p * 1024 + TILE_BYTES) ^ axor);
                    #pragma unroll
                    for (int mi = 0; mi < 2; mi++) {
                        mma16816(acc[mi][2 * p],     ah[mi], bh);
                        mma16816(acc[mi][2 * p],     ah[mi], bl);
                        mma16816(acc[mi][2 * p],     al[mi], bh);
                        mma16816(acc[mi][2 * p + 1], ah[mi], bh + 2);
                        mma16816(acc[mi][2 * p + 1], ah[mi], bl + 2);
                        mma16816(acc[mi][2 * p + 1], al[mi], bh + 2);
                    }
                } else if (NP == 2) {
                    #pragma unroll
                    for (int mi = 0; mi < 2; mi++) {
                        mma16816(acc[mi][2 * p],     ah[mi], bh);
                        mma16816(acc[mi][2 * p],     al[mi], bh);
                        mma16816(acc[mi][2 * p + 1], ah[mi], bh + 2);
                        mma16816(acc[mi][2 * p + 1], al[mi], bh + 2);
                    }
                } else {
                    #pragma unroll
                    for (int mi = 0; mi < 2; mi++) {
                        mma16816(acc[mi][2 * p],     ah[mi], bh);
                        mma16816(acc[mi][2 * p + 1], ah[mi], bh + 2);
                    }
                }
            }
        }
    }

    // ---------------- epilogue -------------------------------------------
    const int mrow = m0 + wm * 32 + (lane >> 2);
    const int nrow = wn * 64 + 2 * (lane & 3);
    #pragma unroll
    for (int mi = 0; mi < 2; mi++) {
        #pragma unroll
        for (int nj = 0; nj < 8; nj++) {
            #pragma unroll
            for (int ci = 0; ci < 4; ci++) {
                const int m = mrow + mi * 16 + (ci >> 1) * 8;
                const long pix = n0 + nrow + nj * 8 + (ci & 1);
                float v = acc[mi][nj][ci];
                if (mode == 3 || mode == 4) v = fmaxf(v + bias[m], 0.f);
                long oidx = -1;
                if (mode == 1 || mode == 3) {
                    oidx = pix * 512 + m;
                } else if (mode == 4) {
                    // final NCHW scatter from DU s-major rows
                    int p = (int)pix;
                    int sD = p / 12288, rem = p % 12288;
                    int img = rem / 96, w2 = rem % 96;
                    int n = img >> 5, ckH = img & 31;
                    int h = ckH * 3 + sD;
                    outF[(((long)n * 512 + m) * 96 + h) * 96 + w2] = v;
                    continue;
                } else if (mode == 5) {
                    // stage2: H-shuffle -> LR act (s-major)
                    int p = (int)pix;
                    int n = p / 2304, rem = p - n * 2304;
                    int h = rem / 48, w = rem - h * 48;
                    int h2 = 2 * h + (m >> 9);
                    int ckW = w / 3, s = w - ckW * 3;
                    long r = (long)s * 6144 + (n * 16 + ckW) * 96 + h2;
                    oidx = r * 512 + (m & 511);
                } else {
                    // mode 6: w_H out -> DU act (s-major)
                    int p = (int)pix;
                    int sL = p / 6144, rem = p % 6144;
                    int img = rem / 96, h2 = rem % 96;
                    int n = img >> 4, ckW = img & 15;
                    int w = ckW * 3 + sL;
                    int w2 = 2 * w + (m >> 9);
                    int ckH = h2 / 3, sD = h2 - ckH * 3;
                    long r = (long)sD * 12288 + (n * 32 + ckH) * 96 + w2;
                    oidx = r * 512 + (m & 511);
                }
                __half h = __float2half_rn(v);
                outHi[oidx] = h;
                if (wantLo)
                    outLo[oidx] = __float2half_rn(v - __half2float(h));
            }
        }
    }
}

// ------------------------- prep kernels -----------------------------------
__device__ __forceinline__ void split_g(float v, __half* hi, __half* lo,
                                        long idx) {
    __half h = __float2half_rn(v);
    hi[idx] = h;
    lo[idx] = __float2half_rn(v - __half2float(h));
}

__global__ void splitW(const float* __restrict__ src, __half* __restrict__ hi,
                       __half* __restrict__ lo, int count) {
    int i = blockIdx.x * 256 + threadIdx.x;
    if (i < count) split_g(src[i], hi, lo, i);
}

// conv weight reorder + split: dst[co*4608 + t*512 + ci]
__global__ void splitWConv(const float* __restrict__ w, __half* __restrict__ hi,
                           __half* __restrict__ lo, int mulL, int mulS) {
    int i = blockIdx.x * 256 + threadIdx.x;
    int ci = i & 511;
    int t = (i >> 9) % 9;
    int co = i / 4608;
    int dl = t / 3, ds = t % 3;
    float v = w[(long)co * 4608 + ci * 9 + dl * mulL + ds * mulS];
    split_g(v, hi, lo, (long)co * 4608 + t * 512 + ci);
}

// x[n,c,h,w] -> B[pix(n,h,w), c] split
__global__ void gatherX(const float* __restrict__ x, __half* __restrict__ bhi,
                        __half* __restrict__ blo) {
    int i = blockIdx.x * 256 + threadIdx.x;
    int c4 = i & 511;
    int pix = i >> 9;
    int n = pix / 2304;
    int p = pix - n * 2304;
    const float* xs = x + ((long)n * 2048 + c4 * 4) * 2304 + p;
    long o = (long)pix * 2048 + c4 * 4;
    split_g(xs[0],    bhi, blo, o + 0);
    split_g(xs[2304], bhi, blo, o + 1);
    split_g(xs[4608], bhi, blo, o + 2);
    split_g(xs[6912], bhi, blo, o + 3);
}

// ---------------------------------------------------------------------------
// kernel_launch.  Inputs: x, w_channel, w_w, w_H, w_lr, b_lr, w_du, b_du
// ---------------------------------------------------------------------------
extern "C" void kernel_launch(void* const* d_in, const int* in_sizes, int n_in,
                              void* d_out, int out_size) {
    const float* x         = (const float*)d_in[0];
    const float* w_channel = (const float*)d_in[1];
    const float* w_w       = (const float*)d_in[2];
    const float* w_H       = (const float*)d_in[3];
    const float* w_lr      = (const float*)d_in[4];
    const float* b_lr      = (const float*)d_in[5];
    const float* w_du      = (const float*)d_in[6];
    const float* b_du      = (const float*)d_in[7];
    float* out = (float*)d_out;

    __half *aHi, *aLo, *bHi, *bLo, *cHi, *cLo, *B2hi, *B2lo;
    __half *wch_hi, *wch_lo, *ww_hi, *ww_lo, *wH_hi, *wH_lo;
    __half *wlr_hi, *wlr_lo, *wdu_hi, *wdu_lo;
    cudaGetSymbolAddress((void**)&aHi, g_aHi);
    cudaGetSymbolAddress((void**)&aLo, g_aLo);
    cudaGetSymbolAddress((void**)&bHi, g_bHi);
    cudaGetSymbolAddress((void**)&bLo, g_bLo);
    cudaGetSymbolAddress((void**)&cHi, g_cHi);
    cudaGetSymbolAddress((void**)&cLo, g_cLo);
    cudaGetSymbolAddress((void**)&B2hi, g_B2hi);
    cudaGetSymbolAddress((void**)&B2lo, g_B2lo);
    cudaGetSymbolAddress((void**)&wch_hi, g_wch_hi);
    cudaGetSymbolAddress((void**)&wch_lo, g_wch_lo);
    cudaGetSymbolAddress((void**)&ww_hi, g_ww_hi);
    cudaGetSymbolAddress((void**)&ww_lo, g_ww_lo);
    cudaGetSymbolAddress((void**)&wH_hi, g_wH_hi);
    cudaGetSymbolAddress((void**)&wH_lo, g_wH_lo);
    cudaGetSymbolAddress((void**)&wlr_hi, g_wlr_hi);
    cudaGetSymbolAddress((void**)&wlr_lo, g_wlr_lo);
    cudaGetSymbolAddress((void**)&wdu_hi, g_wdu_hi);
    cudaGetSymbolAddress((void**)&wdu_lo, g_wdu_lo);

    cudaFuncSetAttribute(gemm_hmma<3>, cudaFuncAttributeMaxDynamicSharedMemorySize,
                         SMEM_TOTAL);
    cudaFuncSetAttribute(gemm_hmma<1>, cudaFuncAttributeMaxDynamicSharedMemorySize,
                         SMEM_TOTAL);

    // weight prep
    splitW<<<(512 * 2048) / 256, 256>>>(w_channel, wch_hi, wch_lo, 512 * 2048);
    splitW<<<(1024 * 512) / 256, 256>>>(w_w, ww_hi, ww_lo, 1024 * 512);
    splitW<<<(1024 * 512) / 256, 256>>>(w_H, wH_hi, wH_lo, 1024 * 512);
    splitWConv<<<(512 * 4608) / 256, 256>>>(w_lr, wlr_hi, wlr_lo, 3, 1);
    splitWConv<<<(512 * 4608) / 256, 256>>>(w_du, wdu_hi, wdu_lo, 1, 3);

    // stage 1: split(x) -> a [9216,2048]; y1 = w_channel @ x -> split B2
    gatherX<<<(9216 * 512) / 256, 256>>>(x, aHi, aLo);
    gemm_hmma<3><<<dim3(4, 72), 256, SMEM_TOTAL>>>(
        wch_hi, wch_lo, aHi, aLo, 2048, 2048, 0, 0, 1, 1, nullptr,
        nullptr, B2hi, B2lo);

    // stage 2: w_w @ y1, epilogue = H-shuffle -> LR act (s-major, hi only)
    gemm_hmma<3><<<dim3(8, 72), 256, SMEM_TOTAL>>>(
        ww_hi, ww_lo, B2hi, B2lo, 512, 512, 0, 0, 5, 0, nullptr,
        nullptr, bHi, bLo);

    // convLR pass 1 (S=6144, 1-product fp16 weights) -> c hi only
    gemm_hmma<1><<<dim3(4, 144), 256, SMEM_TOTAL>>>(
        wlr_hi, wlr_lo, bHi, bLo, 4608, 512, 1, 6144, 3, 0, b_lr,
        nullptr, cHi, cLo);

    // convLR pass 2 (1-product) -> a hi+lo (feeds 3-product w_H)
    gemm_hmma<1><<<dim3(4, 144), 256, SMEM_TOTAL>>>(
        wlr_hi, wlr_lo, cHi, cLo, 4608, 512, 1, 6144, 3, 1, b_lr,
        nullptr, aHi, aLo);

    // w_H stage (3-product): epilogue = W-shuffle -> DU act (hi only)
    gemm_hmma<3><<<dim3(8, 144), 256, SMEM_TOTAL>>>(
        wH_hi, wH_lo, aHi, aLo, 512, 512, 0, 0, 6, 0, nullptr,
        nullptr, bHi, bLo);

    // convDU pass 1 (S=12288, 1-product) -> a hi only
    gemm_hmma<1><<<dim3(4, 288), 256, SMEM_TOTAL>>>(
        wdu_hi, wdu_lo, bHi, bLo, 4608, 512, 1, 12288, 3, 0, b_du,
        nullptr, aHi, aLo);

    // convDU pass 2 (1-product) -> final NCHW output
    gemm_hmma<1><<<dim3(4, 288), 256, SMEM_TOTAL>>>(
        wdu_hi, wdu_lo, aHi, aLo, 4608, 512, 1, 12288, 4, 0, b_du,
        out, nullptr, nullptr);
}

// round 16
// speedup vs baseline: 1.6136x; 1.0833x over previous
#include <cuda_runtime.h>
#include <cuda_fp16.h>
#include <cstdint>

// ===========================================================================
// SSRupsampling via HMMA (mma.sync m16n8k16, fp32 accum), fp16 split.
// 1x1 GEMMs: 3-product (128x128 block, 32x64 warp tiles, 256 thr).
// Convs: 1-product fp16-weight kernel with 64x64 warp tiles, 128 thr,
// 4 warps, 2 CTA/SM (128 B smem per MMA). Conv B = shifted view of S-MAJOR
// [pix,512] act (r = s*S + img*96 + l); uniform s per 128-row N-tile ->
// invalid taps skipped. Swizzled smem, cp.async pipeline, single sync per
// chunk. Pixel shuffles fused into GEMM epilogues.
// ===========================================================================

// ------------------------------ scratch -----------------------------------
__device__ __half g_aHi[36864L * 512], g_aLo[36864L * 512];
__device__ __half g_bHi[36864L * 512], g_bLo[36864L * 512];
__device__ __half g_cHi[18432 * 512],  g_cLo[18432 * 512];
__device__ __half g_B2hi[9216 * 512],  g_B2lo[9216 * 512];
__device__ __half g_wch_hi[512 * 2048], g_wch_lo[512 * 2048];
__device__ __half g_ww_hi[1024 * 512],  g_ww_lo[1024 * 512];
__device__ __half g_wH_hi[1024 * 512],  g_wH_lo[1024 * 512];
__device__ __half g_wlr_hi[512 * 4608], g_wlr_lo[512 * 4608];
__device__ __half g_wdu_hi[512 * 4608], g_wdu_lo[512 * 4608];

// ------------------------------ helpers -----------------------------------
__device__ __forceinline__ uint32_t smem_u32(const void* p) {
    uint32_t a;
    asm("{ .reg .u64 t; cvta.to.shared.u64 t, %1; cvt.u32.u64 %0, t; }"
        : "=r"(a) : "l"(p));
    return a;
}
__device__ __forceinline__ void ldsm_x4(uint32_t* r, uint32_t addr) {
    asm volatile("ldmatrix.sync.aligned.m8n8.x4.shared.b16 {%0,%1,%2,%3}, [%4];"
                 : "=r"(r[0]), "=r"(r[1]), "=r"(r[2]), "=r"(r[3]) : "r"(addr));
}
__device__ __forceinline__ void mma16816(float* c, const uint32_t* a,
                                         const uint32_t* b) {
    asm volatile(
        "mma.sync.aligned.m16n8k16.row.col.f32.f16.f16.f32 "
        "{%0,%1,%2,%3}, {%4,%5,%6,%7}, {%8,%9}, {%0,%1,%2,%3};"
        : "+f"(c[0]), "+f"(c[1]), "+f"(c[2]), "+f"(c[3])
        : "r"(a[0]), "r"(a[1]), "r"(a[2]), "r"(a[3]), "r"(b[0]), "r"(b[1]));
}
__device__ __forceinline__ void cp16(uint32_t sa, const void* ga) {
    asm volatile("cp.async.cg.shared.global [%0], [%1], 16;"
                 :: "r"(sa), "l"(ga));
}
__device__ __forceinline__ void cp16p(uint32_t sa, const void* ga, int sz) {
    asm volatile("cp.async.cg.shared.global [%0], [%1], 16, %2;"
                 :: "r"(sa), "l"(ga), "r"(sz));
}

#define BK 32
#define TILE_BYTES 8192            // 128 rows x 64B, swizzled
#define SMEM_1X1 98304             // 3-product kernel: 4 tiles x 3 stages
#define SMEM_CONV 49152            // conv kernel: 2 tiles x 3 stages

// swizzled byte offset of the 16B unit (row, lcol), row 0..127, lcol 0..3
__device__ __forceinline__ uint32_t swz(int row, int lcol) {
    return (uint32_t)((row >> 1) * 128 +
                      ((((row & 1) * 4 + lcol) ^ ((row >> 1) & 7)) * 16));
}

// ---------------------------------------------------------------------------
// 3-product GEMM for the 1x1 stages (unchanged R14 machinery, NP=3 path).
// Block 128x128, 256 thr, 8 warps (4m x 2n), warp 32x64, depth 3.
// Modes: 1 split [pix,512]; 5 split + H-shuffle; 6 split + W-shuffle.
// ---------------------------------------------------------------------------
__global__ __launch_bounds__(256, 2)
void gemm_hmma3(const __half* __restrict__ Ahi, const __half* __restrict__ Alo,
                const __half* __restrict__ Bhi, const __half* __restrict__ Blo,
                int K, int Kb, int mode, int wantLo,
                __half* __restrict__ outHi, __half* __restrict__ outLo) {
    constexpr int STG = 4 * TILE_BYTES;
    constexpr int NST = 3;
    constexpr int OFF_ALO = TILE_BYTES;
    constexpr int OFF_BHI = 2 * TILE_BYTES;
    constexpr int OFF_BLO = 3 * TILE_BYTES;

    extern __shared__ char smem[];
    const uint32_t sb = smem_u32(smem);
    const int tid = threadIdx.x;
    const int lane = tid & 31, wid = tid >> 5;
    const int wm = wid >> 1, wn = wid & 1;
    const int m0 = blockIdx.x * 128;
    const long n0 = (long)blockIdx.y * 128;

    const __half* gA0 = Ahi + (long)m0 * K;
    const __half* gA1 = Alo + (long)m0 * K;
    const __half* gB0 = Bhi + n0 * Kb;
    const __half* gB1 = Blo + n0 * Kb;

    const int lrow0 = tid >> 2, lcol = tid & 3;
    const int lrow1 = lrow0 + 64;
    const uint32_t sw0 = swz(lrow0, lcol);
    const uint32_t sw1 = swz(lrow1, lcol);

    const int lg = lane >> 3, lr = lane & 7;
    const uint32_t abase = swz(wm * 32 + (lg & 1) * 8 + lr, lg >> 1);
    const uint32_t bbase = swz(wn * 64 + (lg >> 1) * 8 + lr, lg & 1);

    float acc[2][8][4];
    #pragma unroll
    for (int i = 0; i < 2; i++)
        #pragma unroll
        for (int j = 0; j < 8; j++)
            #pragma unroll
            for (int c = 0; c < 4; c++) acc[i][j][c] = 0.f;

    const int nC = K / BK;

    auto issue = [&](int kc) {
        const uint32_t so = sb + (kc % NST) * STG;
        const long kb = (long)kc * BK;
        const long ga0 = (long)lrow0 * K + kb + lcol * 8;
        const long ga1 = (long)lrow1 * K + kb + lcol * 8;
        cp16(so + sw0, gA0 + ga0);
        cp16(so + sw1, gA0 + ga1);
        cp16(so + OFF_ALO + sw0, gA1 + ga0);
        cp16(so + OFF_ALO + sw1, gA1 + ga1);
        const long gb0 = (long)lrow0 * Kb + kb + lcol * 8;
        const long gb1 = (long)lrow1 * Kb + kb + lcol * 8;
        cp16(so + OFF_BHI + sw0, gB0 + gb0);
        cp16(so + OFF_BHI + sw1, gB0 + gb1);
        cp16(so + OFF_BLO + sw0, gB1 + gb0);
        cp16(so + OFF_BLO + sw1, gB1 + gb1);
        asm volatile("cp.async.commit_group;" ::: "memory");
    };

    issue(0);
    issue(1);
    for (int kc = 0; kc < nC; kc++) {
        if (kc + 1 < nC) {
            asm volatile("cp.async.wait_group 1;" ::: "memory");
        } else {
            asm volatile("cp.async.wait_group 0;" ::: "memory");
        }
        __syncthreads();
        if (kc + 2 < nC) issue(kc + 2);

        const uint32_t so = sb + (kc % NST) * STG;
        #pragma unroll
        for (int ks = 0; ks < 2; ks++) {
            const uint32_t axor = ks * 32;
            uint32_t ah[2][4], al[2][4];
            const uint32_t ab = so + abase;
            ldsm_x4(ah[0], (ab) ^ axor);
            ldsm_x4(ah[1], (ab + 1024) ^ axor);
            ldsm_x4(al[0], (ab + OFF_ALO) ^ axor);
            ldsm_x4(al[1], (ab + OFF_ALO + 1024) ^ axor);
            const uint32_t bb = so + OFF_BHI + bbase;
            #pragma unroll
            for (int p = 0; p < 4; p++) {
                uint32_t bh[4], bl[4];
                ldsm_x4(bh, (bb + p * 1024) ^ axor);
                ldsm_x4(bl, (bb + p * 1024 + TILE_BYTES) ^ axor);
                #pragma unroll
                for (int mi = 0; mi < 2; mi++) {
                    mma16816(acc[mi][2 * p],     ah[mi], bh);
                    mma16816(acc[mi][2 * p],     ah[mi], bl);
                    mma16816(acc[mi][2 * p],     al[mi], bh);
                    mma16816(acc[mi][2 * p + 1], ah[mi], bh + 2);
                    mma16816(acc[mi][2 * p + 1], ah[mi], bl + 2);
                    mma16816(acc[mi][2 * p + 1], al[mi], bh + 2);
                }
            }
        }
    }

    // epilogue
    const int mrow = m0 + wm * 32 + (lane >> 2);
    const int nrow = wn * 64 + 2 * (lane & 3);
    #pragma unroll
    for (int mi = 0; mi < 2; mi++) {
        #pragma unroll
        for (int nj = 0; nj < 8; nj++) {
            #pragma unroll
            for (int ci = 0; ci < 4; ci++) {
                const int m = mrow + mi * 16 + (ci >> 1) * 8;
                const long pix = n0 + nrow + nj * 8 + (ci & 1);
                float v = acc[mi][nj][ci];
                long oidx;
                if (mode == 1) {
                    oidx = pix * 512 + m;
                } else if (mode == 5) {       // H-shuffle -> LR act (s-major)
                    int p = (int)pix;
                    int n = p / 2304, rem = p - n * 2304;
                    int h = rem / 48, w = rem - h * 48;
                    int h2 = 2 * h + (m >> 9);
                    int ckW = w / 3, s = w - ckW * 3;
                    long r = (long)s * 6144 + (n * 16 + ckW) * 96 + h2;
                    oidx = r * 512 + (m & 511);
                } else {                      // mode 6: W-shuffle -> DU act
                    int p = (int)pix;
                    int sL = p / 6144, rem = p % 6144;
                    int img = rem / 96, h2 = rem % 96;
                    int n = img >> 4, ckW = img & 15;
                    int w = ckW * 3 + sL;
                    int w2 = 2 * w + (m >> 9);
                    int ckH = h2 / 3, sD = h2 - ckH * 3;
                    long r = (long)sD * 12288 + (n * 32 + ckH) * 96 + w2;
                    oidx = r * 512 + (m & 511);
                }
                __half h = __float2half_rn(v);
                outHi[oidx] = h;
                if (wantLo)
                    outLo[oidx] = __float2half_rn(v - __half2float(h));
            }
        }
    }
}

// ---------------------------------------------------------------------------
// 1-product conv GEMM: D = Wh * Ah, fp32 accum, bias+relu.
// Block 128x128, 128 thr, 4 warps (2m x 2n), warp tile 64x64 (128 B/MMA).
// Stage = 2 tiles (16 KB), depth 3 -> 48 KB/CTA, 2 CTA/SM.
// B from S-MAJOR [Npix,512] act; uniform s per N-tile; valid taps only.
// Modes: 3 bias+relu split [pix,512] (wantLo opt); 4 bias+relu NCHW scatter.
// ---------------------------------------------------------------------------
__global__ __launch_bounds__(128, 2)
void gemm_conv1(const __half* __restrict__ Whi, const __half* __restrict__ Ahi,
                int K, int Kb, int S, int mode, int wantLo,
                const float* __restrict__ bias, float* __restrict__ outF,
                __half* __restrict__ outHi, __half* __restrict__ outLo) {
    constexpr int STG = 2 * TILE_BYTES;   // A tile + B tile
    constexpr int NST = 3;
    constexpr int OFF_B = TILE_BYTES;

    extern __shared__ char smem[];
    const uint32_t sb = smem_u32(smem);
    const int tid = threadIdx.x;
    const int lane = tid & 31, wid = tid >> 5;
    const int wm = wid >> 1, wn = wid & 1;     // 2m x 2n
    const int m0 = blockIdx.x * 128;
    const long n0 = (long)blockIdx.y * 128;

    const __half* gA = Whi + (long)m0 * K;     // weights [128, K]
    const __half* gB = Ahi + n0 * Kb;          // act rows

    const int lrow = tid >> 2, lcol = tid & 3; // rows lrow+32i, i=0..3
    uint32_t swr[4];
    int lv[4];
    #pragma unroll
    for (int i = 0; i < 4; i++) {
        swr[i] = swz(lrow + 32 * i, lcol);
        lv[i] = (int)((n0 + lrow + 32 * i) % 96);
    }

    // s uniform per tile
    const int sTile = (int)(n0 / S);
    const int nds = (sTile == 1) ? 3 : 2;
    const int dsmin = (sTile == 0) ? 0 : -1;

    const int lg = lane >> 3, lr = lane & 7;
    const uint32_t abase = swz(wm * 64 + (lg & 1) * 8 + lr, lg >> 1);
    const uint32_t bbase = swz(wn * 64 + (lg >> 1) * 8 + lr, lg & 1);

    float acc[4][8][4];
    #pragma unroll
    for (int i = 0; i < 4; i++)
        #pragma unroll
        for (int j = 0; j < 8; j++)
            #pragma unroll
            for (int c = 0; c < 4; c++) acc[i][j][c] = 0.f;

    const int nC = 3 * nds * 16;

    auto issue = [&](int kc) {
        const uint32_t so = sb + (kc % NST) * STG;
        const int ti = kc >> 4;
        const int dlm = ti / nds - 1;
        const int dsm = dsmin + ti % nds;
        const int t = (dlm + 1) * 3 + (dsm + 1);
        const int koff = (kc & 15) * 32 + lcol * 8;
        const long rs = (long)(dlm + dsm * S) * Kb;
        #pragma unroll
        for (int i = 0; i < 4; i++) {
            const int row = lrow + 32 * i;
            cp16(so + swr[i], gA + (long)row * K + t * 512 + koff);
            const int v = ((unsigned)(lv[i] + dlm) < 96u) ? 16 : 0;
            cp16p(so + OFF_B + swr[i], gB + (long)row * Kb + rs + koff, v);
        }
        asm volatile("cp.async.commit_group;" ::: "memory");
    };

    issue(0);
    issue(1);
    for (int kc = 0; kc < nC; kc++) {
        if (kc + 1 < nC) {
            asm volatile("cp.async.wait_group 1;" ::: "memory");
        } else {
            asm volatile("cp.async.wait_group 0;" ::: "memory");
        }
        __syncthreads();
        if (kc + 2 < nC) issue(kc + 2);

        const uint32_t so = sb + (kc % NST) * STG;
        #pragma unroll
        for (int ks = 0; ks < 2; ks++) {
            const uint32_t axor = ks * 32;
            uint32_t ah[4][4];
            const uint32_t ab = so + abase;
            #pragma unroll
            for (int mi = 0; mi < 4; mi++)
                ldsm_x4(ah[mi], (ab + mi * 1024) ^ axor);
            const uint32_t bb = so + OFF_B + bbase;
            #pragma unroll
            for (int p = 0; p < 4; p++) {
                uint32_t bh[4];
                ldsm_x4(bh, (bb + p * 1024) ^ axor);
                #pragma unroll
                for (int mi = 0; mi < 4; mi++) {
                    mma16816(acc[mi][2 * p],     ah[mi], bh);
                    mma16816(acc[mi][2 * p + 1], ah[mi], bh + 2);
                }
            }
        }
    }

    // epilogue: bias + relu
    const int mrow = m0 + wm * 64 + (lane >> 2);
    const int nrow = wn * 64 + 2 * (lane & 3);
    #pragma unroll
    for (int mi = 0; mi < 4; mi++) {
        #pragma unroll
        for (int nj = 0; nj < 8; nj++) {
            #pragma unroll
            for (int ci = 0; ci < 4; ci++) {
                const int m = mrow + mi * 16 + (ci >> 1) * 8;
                const long pix = n0 + nrow + nj * 8 + (ci & 1);
                float v = fmaxf(acc[mi][nj][ci] + bias[m], 0.f);
                if (mode == 4) {
                    // final NCHW scatter from DU s-major rows
                    int p = (int)pix;
                    int sD = p / 12288, rem = p % 12288;
                    int img = rem / 96, w2 = rem % 96;
                    int n = img >> 5, ckH = img & 31;
                    int h = ckH * 3 + sD;
                    outF[(((long)n * 512 + m) * 96 + h) * 96 + w2] = v;
                } else {
                    const long oidx = pix * 512 + m;
                    __half h = __float2half_rn(v);
                    outHi[oidx] = h;
                    if (wantLo)
                        outLo[oidx] = __float2half_rn(v - __half2float(h));
                }
            }
        }
    }
}

// ------------------------- prep kernels -----------------------------------
__device__ __forceinline__ void split_g(float v, __half* hi, __half* lo,
                                        long idx) {
    __half h = __float2half_rn(v);
    hi[idx] = h;
    lo[idx] = __float2half_rn(v - __half2float(h));
}

__global__ void splitW(const float* __restrict__ src, __half* __restrict__ hi,
                       __half* __restrict__ lo, int count) {
    int i = blockIdx.x * 256 + threadIdx.x;
    if (i < count) split_g(src[i], hi, lo, i);
}

// conv weight reorder + split: dst[co*4608 + t*512 + ci]
__global__ void splitWConv(const float* __restrict__ w, __half* __restrict__ hi,
                           __half* __restrict__ lo, int mulL, int mulS) {
    int i = blockIdx.x * 256 + threadIdx.x;
    int ci = i & 511;
    int t = (i >> 9) % 9;
    int co = i / 4608;
    int dl = t / 3, ds = t % 3;
    float v = w[(long)co * 4608 + ci * 9 + dl * mulL + ds * mulS];
    split_g(v, hi, lo, (long)co * 4608 + t * 512 + ci);
}

// x[n,c,h,w] -> B[pix(n,h,w), c] split
__global__ void gatherX(const float* __restrict__ x, __half* __restrict__ bhi,
                        __half* __restrict__ blo) {
    int i = blockIdx.x * 256 + threadIdx.x;
    int c4 = i & 511;
    int pix = i >> 9;
    int n = pix / 2304;
    int p = pix - n * 2304;
    const float* xs = x + ((long)n * 2048 + c4 * 4) * 2304 + p;
    long o = (long)pix * 2048 + c4 * 4;
    split_g(xs[0],    bhi, blo, o + 0);
    split_g(xs[2304], bhi, blo, o + 1);
    split_g(xs[4608], bhi, blo, o + 2);
    split_g(xs[6912], bhi, blo, o + 3);
}

// ---------------------------------------------------------------------------
// kernel_launch.  Inputs: x, w_channel, w_w, w_H, w_lr, b_lr, w_du, b_du
// ---------------------------------------------------------------------------
extern "C" void kernel_launch(void* const* d_in, const int* in_sizes, int n_in,
                              void* d_out, int out_size) {
    const float* x         = (const float*)d_in[0];
    const float* w_channel = (const float*)d_in[1];
    const float* w_w       = (const float*)d_in[2];
    const float* w_H       = (const float*)d_in[3];
    const float* w_lr      = (const float*)d_in[4];
    const float* b_lr      = (const float*)d_in[5];
    const float* w_du      = (const float*)d_in[6];
    const float* b_du      = (const float*)d_in[7];
    float* out = (float*)d_out;

    __half *aHi, *aLo, *bHi, *bLo, *cHi, *cLo, *B2hi, *B2lo;
    __half *wch_hi, *wch_lo, *ww_hi, *ww_lo, *wH_hi, *wH_lo;
    __half *wlr_hi, *wlr_lo, *wdu_hi, *wdu_lo;
    cudaGetSymbolAddress((void**)&aHi, g_aHi);
    cudaGetSymbolAddress((void**)&aLo, g_aLo);
    cudaGetSymbolAddress((void**)&bHi, g_bHi);
    cudaGetSymbolAddress((void**)&bLo, g_bLo);
    cudaGetSymbolAddress((void**)&cHi, g_cHi);
    cudaGetSymbolAddress((void**)&cLo, g_cLo);
    cudaGetSymbolAddress((void**)&B2hi, g_B2hi);
    cudaGetSymbolAddress((void**)&B2lo, g_B2lo);
    cudaGetSymbolAddress((void**)&wch_hi, g_wch_hi);
    cudaGetSymbolAddress((void**)&wch_lo, g_wch_lo);
    cudaGetSymbolAddress((void**)&ww_hi, g_ww_hi);
    cudaGetSymbolAddress((void**)&ww_lo, g_ww_lo);
    cudaGetSymbolAddress((void**)&wH_hi, g_wH_hi);
    cudaGetSymbolAddress((void**)&wH_lo, g_wH_lo);
    cudaGetSymbolAddress((void**)&wlr_hi, g_wlr_hi);
    cudaGetSymbolAddress((void**)&wlr_lo, g_wlr_lo);
    cudaGetSymbolAddress((void**)&wdu_hi, g_wdu_hi);
    cudaGetSymbolAddress((void**)&wdu_lo, g_wdu_lo);

    cudaFuncSetAttribute(gemm_hmma3, cudaFuncAttributeMaxDynamicSharedMemorySize,
                         SMEM_1X1);
    cudaFuncSetAttribute(gemm_conv1, cudaFuncAttributeMaxDynamicSharedMemorySize,
                         SMEM_CONV);

    // weight prep
    splitW<<<(512 * 2048) / 256, 256>>>(w_channel, wch_hi, wch_lo, 512 * 2048);
    splitW<<<(1024 * 512) / 256, 256>>>(w_w, ww_hi, ww_lo, 1024 * 512);
    splitW<<<(1024 * 512) / 256, 256>>>(w_H, wH_hi, wH_lo, 1024 * 512);
    splitWConv<<<(512 * 4608) / 256, 256>>>(w_lr, wlr_hi, wlr_lo, 3, 1);
    splitWConv<<<(512 * 4608) / 256, 256>>>(w_du, wdu_hi, wdu_lo, 1, 3);

    // stage 1: split(x) -> a [9216,2048]; y1 = w_channel @ x -> split B2
    gatherX<<<(9216 * 512) / 256, 256>>>(x, aHi, aLo);
    gemm_hmma3<<<dim3(4, 72), 256, SMEM_1X1>>>(
        wch_hi, wch_lo, aHi, aLo, 2048, 2048, 1, 1, B2hi, B2lo);

    // stage 2: w_w @ y1, epilogue = H-shuffle -> LR act (s-major, hi only)
    gemm_hmma3<<<dim3(8, 72), 256, SMEM_1X1>>>(
        ww_hi, ww_lo, B2hi, B2lo, 512, 512, 5, 0, bHi, bLo);

    // convLR pass 1 (S=6144, fp16 weights) -> c hi only
    gemm_conv1<<<dim3(4, 144), 128, SMEM_CONV>>>(
        wlr_hi, bHi, 4608, 512, 6144, 3, 0, b_lr, nullptr, cHi, cLo);

    // convLR pass 2 -> a hi+lo (feeds 3-product w_H)
    gemm_conv1<<<dim3(4, 144), 128, SMEM_CONV>>>(
        wlr_hi, cHi, 4608, 512, 6144, 3, 1, b_lr, nullptr, aHi, aLo);

    // w_H stage (3-product): epilogue = W-shuffle -> DU act (hi only)
    gemm_hmma3<<<dim3(8, 144), 256, SMEM_1X1>>>(
        wH_hi, wH_lo, aHi, aLo, 512, 512, 6, 0, bHi, bLo);

    // convDU pass 1 (S=12288) -> a hi only
    gemm_conv1<<<dim3(4, 288), 128, SMEM_CONV>>>(
        wdu_hi, bHi, 4608, 512, 12288, 3, 0, b_du, nullptr, aHi, aLo);

    // convDU pass 2 -> final NCHW output
    gemm_conv1<<<dim3(4, 288), 128, SMEM_CONV>>>(
        wdu_hi, aHi, 4608, 512, 12288, 4, 0, b_du, out, nullptr, nullptr);
}

// round 17
// speedup vs baseline: 1.7979x; 1.1142x over previous
#include <cuda_runtime.h>
#include <cuda_fp16.h>
#include <cstdint>

// ===========================================================================
// SSRupsampling, all-HMMA (mma.sync m16n8k16, fp32 accum).
// 1x1 GEMMs: 2-product (weights hi+lo x act-hi), wide-tile kernel.
// Convs: 1-product (fp16 weights x act-hi), wide-tile kernel.
// Both: 128x128 block, 128 thr, 4 warps (2m x 2n), 64x64 warp tiles,
// 2 CTA/SM, swizzled smem, 3-deep cp.async pipeline, 1 sync/chunk.
// Conv B = shifted view of S-MAJOR [pix,512] act (r = s*S + img*96 + l);
// uniform s per 128-row N-tile -> invalid taps skipped.
// Pixel shuffles fused into GEMM epilogues. No lo-activations anywhere.
// ===========================================================================

// ------------------------------ scratch -----------------------------------
__device__ __half g_aHi[36864L * 512];
__device__ __half g_bHi[36864L * 512];
__device__ __half g_cHi[18432 * 512];
__device__ __half g_B2hi[9216 * 512];
__device__ __half g_xHi[9216 * 2048];
__device__ __half g_wch_hi[512 * 2048], g_wch_lo[512 * 2048];
__device__ __half g_ww_hi[1024 * 512],  g_ww_lo[1024 * 512];
__device__ __half g_wH_hi[1024 * 512],  g_wH_lo[1024 * 512];
__device__ __half g_wlr_hi[512 * 4608], g_wlr_lo[512 * 4608];
__device__ __half g_wdu_hi[512 * 4608], g_wdu_lo[512 * 4608];

// ------------------------------ helpers -----------------------------------
__device__ __forceinline__ uint32_t smem_u32(const void* p) {
    uint32_t a;
    asm("{ .reg .u64 t; cvta.to.shared.u64 t, %1; cvt.u32.u64 %0, t; }"
        : "=r"(a) : "l"(p));
    return a;
}
__device__ __forceinline__ void ldsm_x4(uint32_t* r, uint32_t addr) {
    asm volatile("ldmatrix.sync.aligned.m8n8.x4.shared.b16 {%0,%1,%2,%3}, [%4];"
                 : "=r"(r[0]), "=r"(r[1]), "=r"(r[2]), "=r"(r[3]) : "r"(addr));
}
__device__ __forceinline__ void mma16816(float* c, const uint32_t* a,
                                         const uint32_t* b) {
    asm volatile(
        "mma.sync.aligned.m16n8k16.row.col.f32.f16.f16.f32 "
        "{%0,%1,%2,%3}, {%4,%5,%6,%7}, {%8,%9}, {%0,%1,%2,%3};"
        : "+f"(c[0]), "+f"(c[1]), "+f"(c[2]), "+f"(c[3])
        : "r"(a[0]), "r"(a[1]), "r"(a[2]), "r"(a[3]), "r"(b[0]), "r"(b[1]));
}
__device__ __forceinline__ void cp16(uint32_t sa, const void* ga) {
    asm volatile("cp.async.cg.shared.global [%0], [%1], 16;"
                 :: "r"(sa), "l"(ga));
}
__device__ __forceinline__ void cp16p(uint32_t sa, const void* ga, int sz) {
    asm volatile("cp.async.cg.shared.global [%0], [%1], 16, %2;"
                 :: "r"(sa), "l"(ga), "r"(sz));
}

#define BK 32
#define TILE_BYTES 8192            // 128 rows x 64B, swizzled
#define SMEM_W2   73728            // 3 tiles x 3 stages
#define SMEM_CONV 49152            // 2 tiles x 3 stages

// swizzled byte offset of the 16B unit (row, lcol), row 0..127, lcol 0..3
__device__ __forceinline__ uint32_t swz(int row, int lcol) {
    return (uint32_t)((row >> 1) * 128 +
                      ((((row & 1) * 4 + lcol) ^ ((row >> 1) & 7)) * 16));
}

// ---------------------------------------------------------------------------
// 2-product 1x1 GEMM: D = (Wh + Wl) * Ah.  Wide tile: block 128x128,
// 128 thr, 4 warps (2m x 2n), warp 64x64. Stage = 3 tiles (24 KB), depth 3.
// Modes: 1 plain [pix,512]; 5 + H-shuffle -> LR act; 6 + W-shuffle -> DU act.
// All outputs fp16 hi only.
// ---------------------------------------------------------------------------
__global__ __launch_bounds__(128, 2)
void gemm_w2(const __half* __restrict__ Whi, const __half* __restrict__ Wlo,
             const __half* __restrict__ Act, int K, int Kb, int mode,
             __half* __restrict__ outHi) {
    constexpr int STG = 3 * TILE_BYTES;
    constexpr int NST = 3;
    constexpr int OFF_WLO = TILE_BYTES;
    constexpr int OFF_B = 2 * TILE_BYTES;

    extern __shared__ char smem[];
    const uint32_t sb = smem_u32(smem);
    const int tid = threadIdx.x;
    const int lane = tid & 31, wid = tid >> 5;
    const int wm = wid >> 1, wn = wid & 1;
    const int m0 = blockIdx.x * 128;
    const long n0 = (long)blockIdx.y * 128;

    const __half* gA0 = Whi + (long)m0 * K;
    const __half* gA1 = Wlo + (long)m0 * K;
    const __half* gB = Act + n0 * Kb;

    const int lrow = tid >> 2, lcol = tid & 3;
    uint32_t swr[4];
    #pragma unroll
    for (int i = 0; i < 4; i++) swr[i] = swz(lrow + 32 * i, lcol);

    const int lg = lane >> 3, lr = lane & 7;
    const uint32_t abase = swz(wm * 64 + (lg & 1) * 8 + lr, lg >> 1);
    const uint32_t bbase = swz(wn * 64 + (lg >> 1) * 8 + lr, lg & 1);

    float acc[4][8][4];
    #pragma unroll
    for (int i = 0; i < 4; i++)
        #pragma unroll
        for (int j = 0; j < 8; j++)
            #pragma unroll
            for (int c = 0; c < 4; c++) acc[i][j][c] = 0.f;

    const int nC = K / BK;

    auto issue = [&](int kc) {
        const uint32_t so = sb + (kc % NST) * STG;
        const long kb = (long)kc * BK;
        #pragma unroll
        for (int i = 0; i < 4; i++) {
            const int row = lrow + 32 * i;
            const long ga = (long)row * K + kb + lcol * 8;
            cp16(so + swr[i], gA0 + ga);
            cp16(so + OFF_WLO + swr[i], gA1 + ga);
            cp16(so + OFF_B + swr[i], gB + (long)row * Kb + kb + lcol * 8);
        }
        asm volatile("cp.async.commit_group;" ::: "memory");
    };

    issue(0);
    issue(1);
    for (int kc = 0; kc < nC; kc++) {
        if (kc + 1 < nC) {
            asm volatile("cp.async.wait_group 1;" ::: "memory");
        } else {
            asm volatile("cp.async.wait_group 0;" ::: "memory");
        }
        __syncthreads();
        if (kc + 2 < nC) issue(kc + 2);

        const uint32_t so = sb + (kc % NST) * STG;
        #pragma unroll
        for (int ks = 0; ks < 2; ks++) {
            const uint32_t axor = ks * 32;
            uint32_t ah[4][4], al[4][4];
            const uint32_t ab = so + abase;
            #pragma unroll
            for (int mi = 0; mi < 4; mi++) {
                ldsm_x4(ah[mi], (ab + mi * 1024) ^ axor);
                ldsm_x4(al[mi], (ab + OFF_WLO + mi * 1024) ^ axor);
            }
            const uint32_t bb = so + OFF_B + bbase;
            #pragma unroll
            for (int p = 0; p < 4; p++) {
                uint32_t bh[4];
                ldsm_x4(bh, (bb + p * 1024) ^ axor);
                #pragma unroll
                for (int mi = 0; mi < 4; mi++) {
                    mma16816(acc[mi][2 * p],     ah[mi], bh);
                    mma16816(acc[mi][2 * p],     al[mi], bh);
                    mma16816(acc[mi][2 * p + 1], ah[mi], bh + 2);
                    mma16816(acc[mi][2 * p + 1], al[mi], bh + 2);
                }
            }
        }
    }

    // epilogue (fp16 hi only)
    const int mrow = m0 + wm * 64 + (lane >> 2);
    const int nrow = wn * 64 + 2 * (lane & 3);
    #pragma unroll
    for (int mi = 0; mi < 4; mi++) {
        #pragma unroll
        for (int nj = 0; nj < 8; nj++) {
            #pragma unroll
            for (int ci = 0; ci < 4; ci++) {
                const int m = mrow + mi * 16 + (ci >> 1) * 8;
                const long pix = n0 + nrow + nj * 8 + (ci & 1);
                float v = acc[mi][nj][ci];
                long oidx;
                if (mode == 1) {
                    oidx = pix * 512 + m;
                } else if (mode == 5) {       // H-shuffle -> LR act (s-major)
                    int p = (int)pix;
                    int n = p / 2304, rem = p - n * 2304;
                    int h = rem / 48, w = rem - h * 48;
                    int h2 = 2 * h + (m >> 9);
                    int ckW = w / 3, s = w - ckW * 3;
                    long r = (long)s * 6144 + (n * 16 + ckW) * 96 + h2;
                    oidx = r * 512 + (m & 511);
                } else {                      // mode 6: W-shuffle -> DU act
                    int p = (int)pix;
                    int sL = p / 6144, rem = p % 6144;
                    int img = rem / 96, h2 = rem % 96;
                    int n = img >> 4, ckW = img & 15;
                    int w = ckW * 3 + sL;
                    int w2 = 2 * w + (m >> 9);
                    int ckH = h2 / 3, sD = h2 - ckH * 3;
                    long r = (long)sD * 12288 + (n * 32 + ckH) * 96 + w2;
                    oidx = r * 512 + (m & 511);
                }
                outHi[oidx] = __float2half_rn(v);
            }
        }
    }
}

// ---------------------------------------------------------------------------
// 1-product conv GEMM: D = Wh * Ah, fp32 accum, bias+relu (R15, proven).
// Block 128x128, 128 thr, 4 warps (2m x 2n), warp 64x64, 2 tiles x 3 stages.
// Modes: 3 bias+relu fp16 [pix,512]; 4 bias+relu NCHW scatter.
// ---------------------------------------------------------------------------
__global__ __launch_bounds__(128, 2)
void gemm_conv1(const __half* __restrict__ Whi, const __half* __restrict__ Ahi,
                int K, int Kb, int S, int mode,
                const float* __restrict__ bias, float* __restrict__ outF,
                __half* __restrict__ outHi) {
    constexpr int STG = 2 * TILE_BYTES;
    constexpr int NST = 3;
    constexpr int OFF_B = TILE_BYTES;

    extern __shared__ char smem[];
    const uint32_t sb = smem_u32(smem);
    const int tid = threadIdx.x;
    const int lane = tid & 31, wid = tid >> 5;
    const int wm = wid >> 1, wn = wid & 1;
    const int m0 = blockIdx.x * 128;
    const long n0 = (long)blockIdx.y * 128;

    const __half* gA = Whi + (long)m0 * K;
    const __half* gB = Ahi + n0 * Kb;

    const int lrow = tid >> 2, lcol = tid & 3;
    uint32_t swr[4];
    int lv[4];
    #pragma unroll
    for (int i = 0; i < 4; i++) {
        swr[i] = swz(lrow + 32 * i, lcol);
        lv[i] = (int)((n0 + lrow + 32 * i) % 96);
    }

    const int sTile = (int)(n0 / S);
    const int nds = (sTile == 1) ? 3 : 2;
    const int dsmin = (sTile == 0) ? 0 : -1;

    const int lg = lane >> 3, lr = lane & 7;
    const uint32_t abase = swz(wm * 64 + (lg & 1) * 8 + lr, lg >> 1);
    const uint32_t bbase = swz(wn * 64 + (lg >> 1) * 8 + lr, lg & 1);

    float acc[4][8][4];
    #pragma unroll
    for (int i = 0; i < 4; i++)
        #pragma unroll
        for (int j = 0; j < 8; j++)
            #pragma unroll
            for (int c = 0; c < 4; c++) acc[i][j][c] = 0.f;

    const int nC = 3 * nds * 16;

    auto issue = [&](int kc) {
        const uint32_t so = sb + (kc % NST) * STG;
        const int ti = kc >> 4;
        const int dlm = ti / nds - 1;
        const int dsm = dsmin + ti % nds;
        const int t = (dlm + 1) * 3 + (dsm + 1);
        const int koff = (kc & 15) * 32 + lcol * 8;
        const long rs = (long)(dlm + dsm * S) * Kb;
        #pragma unroll
        for (int i = 0; i < 4; i++) {
            const int row = lrow + 32 * i;
            cp16(so + swr[i], gA + (long)row * K + t * 512 + koff);
            const int v = ((unsigned)(lv[i] + dlm) < 96u) ? 16 : 0;
            cp16p(so + OFF_B + swr[i], gB + (long)row * Kb + rs + koff, v);
        }
        asm volatile("cp.async.commit_group;" ::: "memory");
    };

    issue(0);
    issue(1);
    for (int kc = 0; kc < nC; kc++) {
        if (kc + 1 < nC) {
            asm volatile("cp.async.wait_group 1;" ::: "memory");
        } else {
            asm volatile("cp.async.wait_group 0;" ::: "memory");
        }
        __syncthreads();
        if (kc + 2 < nC) issue(kc + 2);

        const uint32_t so = sb + (kc % NST) * STG;
        #pragma unroll
        for (int ks = 0; ks < 2; ks++) {
            const uint32_t axor = ks * 32;
            uint32_t ah[4][4];
            const uint32_t ab = so + abase;
            #pragma unroll
            for (int mi = 0; mi < 4; mi++)
                ldsm_x4(ah[mi], (ab + mi * 1024) ^ axor);
            const uint32_t bb = so + OFF_B + bbase;
            #pragma unroll
            for (int p = 0; p < 4; p++) {
                uint32_t bh[4];
                ldsm_x4(bh, (bb + p * 1024) ^ axor);
                #pragma unroll
                for (int mi = 0; mi < 4; mi++) {
                    mma16816(acc[mi][2 * p],     ah[mi], bh);
                    mma16816(acc[mi][2 * p + 1], ah[mi], bh + 2);
                }
            }
        }
    }

    // epilogue: bias + relu
    const int mrow = m0 + wm * 64 + (lane >> 2);
    const int nrow = wn * 64 + 2 * (lane & 3);
    #pragma unroll
    for (int mi = 0; mi < 4; mi++) {
        #pragma unroll
        for (int nj = 0; nj < 8; nj++) {
            #pragma unroll
            for (int ci = 0; ci < 4; ci++) {
                const int m = mrow + mi * 16 + (ci >> 1) * 8;
                const long pix = n0 + nrow + nj * 8 + (ci & 1);
                float v = fmaxf(acc[mi][nj][ci] + bias[m], 0.f);
                if (mode == 4) {
                    int p = (int)pix;
                    int sD = p / 12288, rem = p % 12288;
                    int img = rem / 96, w2 = rem % 96;
                    int n = img >> 5, ckH = img & 31;
                    int h = ckH * 3 + sD;
                    outF[(((long)n * 512 + m) * 96 + h) * 96 + w2] = v;
                } else {
                    outHi[pix * 512 + m] = __float2half_rn(v);
                }
            }
        }
    }
}

// ------------------------- prep kernels -----------------------------------
__device__ __forceinline__ void split_g(float v, __half* hi, __half* lo,
                                        long idx) {
    __half h = __float2half_rn(v);
    hi[idx] = h;
    lo[idx] = __float2half_rn(v - __half2float(h));
}

__global__ void splitW(const float* __restrict__ src, __half* __restrict__ hi,
                       __half* __restrict__ lo, int count) {
    int i = blockIdx.x * 256 + threadIdx.x;
    if (i < count) split_g(src[i], hi, lo, i);
}

// conv weight reorder (fp16 hi only): dst[co*4608 + t*512 + ci]
__global__ void convWhi(const float* __restrict__ w, __half* __restrict__ hi,
                        int mulL, int mulS) {
    int i = blockIdx.x * 256 + threadIdx.x;
    int ci = i & 511;
    int t = (i >> 9) % 9;
    int co = i / 4608;
    int dl = t / 3, ds = t % 3;
    hi[(long)co * 4608 + t * 512 + ci] =
        __float2half_rn(w[(long)co * 4608 + ci * 9 + dl * mulL + ds * mulS]);
}

// x[n,c,h,w] -> B[pix(n,h,w), c] fp16 hi
__global__ void gatherX(const float* __restrict__ x, __half* __restrict__ bhi) {
    int i = blockIdx.x * 256 + threadIdx.x;
    int c4 = i & 511;
    int pix = i >> 9;
    int n = pix / 2304;
    int p = pix - n * 2304;
    const float* xs = x + ((long)n * 2048 + c4 * 4) * 2304 + p;
    long o = (long)pix * 2048 + c4 * 4;
    bhi[o + 0] = __float2half_rn(xs[0]);
    bhi[o + 1] = __float2half_rn(xs[2304]);
    bhi[o + 2] = __float2half_rn(xs[4608]);
    bhi[o + 3] = __float2half_rn(xs[6912]);
}

// ---------------------------------------------------------------------------
// kernel_launch.  Inputs: x, w_channel, w_w, w_H, w_lr, b_lr, w_du, b_du
// ---------------------------------------------------------------------------
extern "C" void kernel_launch(void* const* d_in, const int* in_sizes, int n_in,
                              void* d_out, int out_size) {
    const float* x         = (const float*)d_in[0];
    const float* w_channel = (const float*)d_in[1];
    const float* w_w       = (const float*)d_in[2];
    const float* w_H       = (const float*)d_in[3];
    const float* w_lr      = (const float*)d_in[4];
    const float* b_lr      = (const float*)d_in[5];
    const float* w_du      = (const float*)d_in[6];
    const float* b_du      = (const float*)d_in[7];
    float* out = (float*)d_out;

    __half *aHi, *bHi, *cHi, *B2hi, *xHi;
    __half *wch_hi, *wch_lo, *ww_hi, *ww_lo, *wH_hi, *wH_lo;
    __half *wlr_hi, *wdu_hi;
    cudaGetSymbolAddress((void**)&aHi, g_aHi);
    cudaGetSymbolAddress((void**)&bHi, g_bHi);
    cudaGetSymbolAddress((void**)&cHi, g_cHi);
    cudaGetSymbolAddress((void**)&B2hi, g_B2hi);
    cudaGetSymbolAddress((void**)&xHi, g_xHi);
    cudaGetSymbolAddress((void**)&wch_hi, g_wch_hi);
    cudaGetSymbolAddress((void**)&wch_lo, g_wch_lo);
    cudaGetSymbolAddress((void**)&ww_hi, g_ww_hi);
    cudaGetSymbolAddress((void**)&ww_lo, g_ww_lo);
    cudaGetSymbolAddress((void**)&wH_hi, g_wH_hi);
    cudaGetSymbolAddress((void**)&wH_lo, g_wH_lo);
    cudaGetSymbolAddress((void**)&wlr_hi, g_wlr_hi);
    cudaGetSymbolAddress((void**)&wdu_hi, g_wdu_hi);

    cudaFuncSetAttribute(gemm_w2, cudaFuncAttributeMaxDynamicSharedMemorySize,
                         SMEM_W2);
    cudaFuncSetAttribute(gemm_conv1, cudaFuncAttributeMaxDynamicSharedMemorySize,
                         SMEM_CONV);

    // weight prep
    splitW<<<(512 * 2048) / 256, 256>>>(w_channel, wch_hi, wch_lo, 512 * 2048);
    splitW<<<(1024 * 512) / 256, 256>>>(w_w, ww_hi, ww_lo, 1024 * 512);
    splitW<<<(1024 * 512) / 256, 256>>>(w_H, wH_hi, wH_lo, 1024 * 512);
    convWhi<<<(512 * 4608) / 256, 256>>>(w_lr, wlr_hi, 3, 1);
    convWhi<<<(512 * 4608) / 256, 256>>>(w_du, wdu_hi, 1, 3);

    // stage 1: x -> fp16; y1 = w_channel @ x -> B2hi [9216,512]
    gatherX<<<(9216 * 512) / 256, 256>>>(x, xHi);
    gemm_w2<<<dim3(4, 72), 128, SMEM_W2>>>(
        wch_hi, wch_lo, xHi, 2048, 2048, 1, B2hi);

    // stage 2: w_w @ y1, epilogue = H-shuffle -> LR act (s-major) bHi
    gemm_w2<<<dim3(8, 72), 128, SMEM_W2>>>(
        ww_hi, ww_lo, B2hi, 512, 512, 5, bHi);

    // convLR pass 1 (S=6144) -> cHi
    gemm_conv1<<<dim3(4, 144), 128, SMEM_CONV>>>(
        wlr_hi, bHi, 4608, 512, 6144, 3, b_lr, nullptr, cHi);

    // convLR pass 2 -> aHi
    gemm_conv1<<<dim3(4, 144), 128, SMEM_CONV>>>(
        wlr_hi, cHi, 4608, 512, 6144, 3, b_lr, nullptr, aHi);

    // w_H stage: epilogue = W-shuffle -> DU act (s-major) bHi
    gemm_w2<<<dim3(8, 144), 128, SMEM_W2>>>(
        wH_hi, wH_lo, aHi, 512, 512, 6, bHi);

    // convDU pass 1 (S=12288) -> aHi
    gemm_conv1<<<dim3(4, 288), 128, SMEM_CONV>>>(
        wdu_hi, bHi, 4608, 512, 12288, 3, b_du, nullptr, aHi);

    // convDU pass 2 -> final NCHW output
    gemm_conv1<<<dim3(4, 288), 128, SMEM_CONV>>>(
        wdu_hi, aHi, 4608, 512, 12288, 4, b_du, out, nullptr);
}